// round 6
// baseline (speedup 1.0000x reference)
#include <cuda_runtime.h>
#include <math.h>

#define OFFD 131

__device__ float g_qH[512*128*32];
__device__ float g_kH[512*128*32];
__device__ float g_qW[512*128*32];
__device__ float g_kW[512*128*32];
__device__ float g_vH[512*128*256];
__device__ float g_vW[512*128*256];
__device__ float g_p0[128*128*320];
__device__ float g_EH[512*128*128];
__device__ float g_EW[512*128*128];
__device__ float g_cO[512*128*256];
__device__ float g_rO[512*128*256];
__device__ float g_dX[129][2];
__device__ float g_dY[129][2];
__device__ float g_Wt[256*320];   // transposed fused weight [c][o]
__device__ float g_bias[320];

typedef unsigned long long ull;

__device__ __forceinline__ void ffma2(ull& d, ull a, ull b) {
    asm("fma.rn.f32x2 %0, %1, %2, %0;" : "+l"(d) : "l"(a), "l"(b));
}
__device__ __forceinline__ ull dup2(float x) {
    ull r; asm("mov.b64 %0, {%1, %1};" : "=l"(r) : "f"(x)); return r;
}
__device__ __forceinline__ float2 u2f(ull v) {
    float2 f; asm("mov.b64 {%0, %1}, %2;" : "=f"(f.x), "=f"(f.y) : "l"(v)); return f;
}
__device__ __forceinline__ void cpa16(unsigned dst, const float* src) {
    asm volatile("cp.async.cg.shared.global [%0], [%1], 16;" :: "r"(dst), "l"(src));
}
__device__ __forceinline__ void cpa_commit() {
    asm volatile("cp.async.commit_group;");
}
template<int N> __device__ __forceinline__ void cpa_wait() {
    asm volatile("cp.async.wait_group %0;" :: "n"(N));
}

// ---- offset pooling + regloss ----
__global__ void kern_prep(const float* __restrict__ off, float* __restrict__ out, int regIdx)
{
    const int t = threadIdx.x;
    const float inv9 = 1.0f / 9.0f;
    for (int idx = t; idx < 258; idx += 512) {
        int r = idx % 129, ch = idx / 129;
        const float* o = off + ch * OFFD * OFFD;
        float s = 0.f;
        #pragma unroll
        for (int i = 0; i < 3; i++)
            #pragma unroll
            for (int j = 0; j < 3; j++) s += o[(r + i) * OFFD + 64 + j];
        g_dX[r][ch] = s * inv9;
    }
    for (int idx = t; idx < 258; idx += 512) {
        int c = idx % 129, ch = idx / 129;
        const float* o = off + ch * OFFD * OFFD;
        float s = 0.f;
        #pragma unroll
        for (int i = 0; i < 3; i++)
            #pragma unroll
            for (int j = 0; j < 3; j++) s += o[(64 + i) * OFFD + c + j];
        g_dY[c][ch] = s * inv9;
    }
    float s1 = 0.f, s2 = 0.f;
    for (int i = t; i < OFFD * OFFD; i += 512) {
        float d = off[i] - off[OFFD * OFFD + i];
        s1 += d * d;
    }
    for (int i = t; i < 2 * 130 * OFFD; i += 512) {
        int ch = i / (130 * OFFD);
        int rem = i - ch * 130 * OFFD;
        int r = rem / OFFD, c = rem - r * OFFD;
        float d = off[ch * OFFD * OFFD + r * OFFD + c] - off[ch * OFFD * OFFD + (r + 1) * OFFD + c];
        s2 += d * d;
    }
    __shared__ float sh1[512], sh2[512];
    sh1[t] = s1; sh2[t] = s2;
    __syncthreads();
    for (int s = 256; s > 0; s >>= 1) {
        if (t < s) { sh1[t] += sh1[t + s]; sh2[t] += sh2[t + s]; }
        __syncthreads();
    }
    if (t == 0)
        out[regIdx] = sh1[0] / (float)(OFFD * OFFD) + sh2[0] / (float)(2 * 130 * OFFD);
}

// ---- weight transpose: g_Wt[c][o], g_bias[o] ----
__global__ void kern_wt(const float* __restrict__ Wq, const float* __restrict__ bq,
                        const float* __restrict__ Wk, const float* __restrict__ bk,
                        const float* __restrict__ Wv, const float* __restrict__ bv)
{
    const int o = blockIdx.x;
    const int c = threadIdx.x;
    const float* row = (o < 32) ? (Wq + (size_t)o * 256)
                      : (o < 64) ? (Wk + (size_t)(o - 32) * 256)
                                 : (Wv + (size_t)(o - 64) * 256);
    g_Wt[(size_t)c * 320 + o] = row[c];
    if (c == 0)
        g_bias[o] = (o < 32) ? bq[o] : (o < 64) ? bk[o - 32] : bv[o - 64];
}

// ---- fused QKV projection GEMM, cp.async double-buffered ----
// grid (ot=5, h=128, b=4), block 256
__global__ __launch_bounds__(256, 2) void kern_proj(const float* __restrict__ x)
{
    __shared__ __align__(16) char smraw[49152];
    float* XsF = (float*)smraw;             // [2][32][128]
    float* WsF = (float*)(smraw + 32768);   // [2][32][64]
    float (*Ot)[68] = (float (*)[68])smraw; // aliases buffers (used after compute)

    const int ot = blockIdx.x, h = blockIdx.y, b = blockIdx.z;
    const int t = threadIdx.x;
    const int tw = t & 15, to = t >> 4;
    const int o0 = ot * 64;

    const unsigned xs_u = (unsigned)__cvta_generic_to_shared(XsF);
    const unsigned ws_u = (unsigned)__cvta_generic_to_shared(WsF);
    const float* xb = x + ((size_t)b * 256) * 16384 + (size_t)h * 128;

    ull acc2[4][4];
    #pragma unroll
    for (int j = 0; j < 4; j++)
        #pragma unroll
        for (int i = 0; i < 4; i++) acc2[j][i] = 0ULL;

    // prologue loads for kc=0
    {
        #pragma unroll
        for (int r = 0; r < 4; r++) {
            int lin = t + r * 256;
            int row = lin >> 5, col = (lin & 31) << 2;
            cpa16(xs_u + (unsigned)((row * 128 + col) * 4), xb + (size_t)row * 16384 + col);
        }
        #pragma unroll
        for (int r = 0; r < 2; r++) {
            int lin = t + r * 256;
            int row = lin >> 4, o4 = (lin & 15) << 2;
            cpa16(ws_u + (unsigned)((row * 64 + o4) * 4), g_Wt + (size_t)row * 320 + o0 + o4);
        }
        cpa_commit();
    }

    for (int kc = 0; kc < 8; kc++) {
        const int buf = kc & 1;
        if (kc < 7) {
            const int nb = buf ^ 1, kn = kc + 1;
            #pragma unroll
            for (int r = 0; r < 4; r++) {
                int lin = t + r * 256;
                int row = lin >> 5, col = (lin & 31) << 2;
                cpa16(xs_u + (unsigned)((nb * 4096 + row * 128 + col) * 4),
                      xb + (size_t)(kn * 32 + row) * 16384 + col);
            }
            #pragma unroll
            for (int r = 0; r < 2; r++) {
                int lin = t + r * 256;
                int row = lin >> 4, o4 = (lin & 15) << 2;
                cpa16(ws_u + (unsigned)((nb * 2048 + row * 64 + o4) * 4),
                      g_Wt + (size_t)(kn * 32 + row) * 320 + o0 + o4);
            }
            cpa_commit();
            cpa_wait<1>();
        } else {
            cpa_wait<0>();
        }
        __syncthreads();

        const float* Xb = XsF + buf * 4096;
        const float* Wb = WsF + buf * 2048;
        #pragma unroll
        for (int cc = 0; cc < 32; cc++) {
            const ull* xp = (const ull*)(Xb + cc * 128 + tw * 8);
            ull x0 = xp[0], x1 = xp[1], x2 = xp[2], x3 = xp[3];
            float4 wv = *(const float4*)(Wb + cc * 64 + to * 4);
            ull wd[4] = {dup2(wv.x), dup2(wv.y), dup2(wv.z), dup2(wv.w)};
            #pragma unroll
            for (int j = 0; j < 4; j++) {
                ffma2(acc2[j][0], wd[j], x0);
                ffma2(acc2[j][1], wd[j], x1);
                ffma2(acc2[j][2], wd[j], x2);
                ffma2(acc2[j][3], wd[j], x3);
            }
        }
        __syncthreads();
    }

    #pragma unroll
    for (int j = 0; j < 4; j++) {
        float bs = g_bias[o0 + to * 4 + j];
        #pragma unroll
        for (int i2 = 0; i2 < 4; i2++) {
            float2 f = u2f(acc2[j][i2]);
            Ot[tw * 8 + 2 * i2][to * 4 + j]     = f.x + bs;
            Ot[tw * 8 + 2 * i2 + 1][to * 4 + j] = f.y + bs;
        }
    }
    __syncthreads();

    if (ot == 0) {
        int w = t >> 1, half = t & 1;
        const float* src = &Ot[w][half * 32];
        if (b > 0) {
            float* dst = half ? (g_kH + (((size_t)(b * 128 + w)) * 128 + h) * 32)
                              : (g_qH + (((size_t)(b * 128 + w)) * 128 + h) * 32);
            #pragma unroll
            for (int i = 0; i < 8; i++) ((float4*)dst)[i] = ((const float4*)src)[i];
            float* dq = g_qW + ((size_t)(b * 128 + h)) * 4096;
            float* dk = g_kW + ((size_t)(b * 128 + h)) * 4096;
            #pragma unroll
            for (int r = 0; r < 4; r++) {
                int e = (t + r * 256) << 2;
                int wI = e >> 5, cI = e & 31;
                *(float4*)(dq + e) = *(const float4*)&Ot[wI][cI];
                *(float4*)(dk + e) = *(const float4*)&Ot[wI][32 + cI];
            }
        } else {
            float* dst = g_p0 + ((size_t)(h * 128 + w)) * 320 + half * 32;
            #pragma unroll
            for (int i = 0; i < 8; i++) ((float4*)dst)[i] = ((const float4*)src)[i];
        }
    } else {
        const int c0v = (ot - 1) * 64;
        int w = t >> 1, half = t & 1;
        const float* src = &Ot[w][half * 32];
        if (b > 0) {
            float* dst = g_vH + (((size_t)(b * 128 + w)) * 128 + h) * 256 + c0v + half * 32;
            #pragma unroll
            for (int i = 0; i < 8; i++) ((float4*)dst)[i] = ((const float4*)src)[i];
            float* dw = g_vW + ((size_t)(b * 128 + h)) * 32768 + c0v;
            #pragma unroll
            for (int r = 0; r < 8; r++) {
                int e = (t + r * 256) << 2;
                int wI = e >> 6, cI = e & 63;
                *(float4*)(dw + (size_t)wI * 256 + cI) = *(const float4*)&Ot[wI][cI];
            }
        } else {
            float* dst = g_p0 + ((size_t)(h * 128 + w)) * 320 + 64 + c0v + half * 32;
            #pragma unroll
            for (int i = 0; i < 8; i++) ((float4*)dst)[i] = ((const float4*)src)[i];
        }
    }
}

// ---- deformable bilinear sampling of batch-0 lines: grid (16384, 2), block 320 ----
__global__ void kern_sample()
{
    const int pt = blockIdx.x, br = blockIdx.y;
    const int k = pt >> 7, pos = pt & 127;
    float px, py;
    if (br == 0) {
        int r = pos + 1;
        px = (-1.0f + k * 0.015625f) + g_dX[r][0];
        py = (-1.0f + r * 0.015625f) + g_dX[r][1];
    } else {
        int ci = pos + 1;
        px = (-1.0f + ci * 0.015625f) + g_dY[ci][0];
        py = (-1.0f + k * 0.015625f) + g_dY[ci][1];
    }
    float fx = (px + 1.0f) * 0.5f * 127.0f;
    float fy = (py + 1.0f) * 0.5f * 127.0f;
    float x0f = floorf(fx), y0f = floorf(fy);
    float wx = fx - x0f, wy = fy - y0f;
    int x0 = (int)x0f, y0 = (int)y0f;
    bool vx0 = (x0 >= 0) && (x0 < 128);
    bool vx1 = (x0 + 1 >= 0) && (x0 + 1 < 128);
    bool vy0 = (y0 >= 0) && (y0 < 128);
    bool vy1 = (y0 + 1 >= 0) && (y0 + 1 < 128);

    const int c = threadIdx.x;
    float acc = 0.f;
    if (vx0 && vy0) acc += g_p0[((size_t)(y0 * 128 + x0)) * 320 + c] * ((1.f - wx) * (1.f - wy));
    if (vx1 && vy0) acc += g_p0[((size_t)(y0 * 128 + x0 + 1)) * 320 + c] * (wx * (1.f - wy));
    if (vx0 && vy1) acc += g_p0[((size_t)((y0 + 1) * 128 + x0)) * 320 + c] * ((1.f - wx) * wy);
    if (vx1 && vy1) acc += g_p0[((size_t)((y0 + 1) * 128 + x0 + 1)) * 320 + c] * (wx * wy);

    size_t lp = (size_t)k * 128 + pos;
    if (br == 0) {
        if (c < 32)      g_qH[lp * 32 + c] = acc;
        else if (c < 64) g_kH[lp * 32 + (c - 32)] = acc;
        else             g_vH[lp * 256 + (c - 64)] = acc;
    } else {
        if (c < 32)      g_qW[lp * 32 + c] = acc;
        else if (c < 64) g_kW[lp * 32 + (c - 32)] = acc;
        else             g_vW[lp * 256 + (c - 64)] = acc;
    }
}

// ---- per-line energy GEMM E = Q @ K^T: grid (512, 2), block 256 ----
__global__ __launch_bounds__(256) void kern_energy()
{
    __shared__ __align__(16) float Qt[32][132];
    __shared__ __align__(16) float Kt[32][132];
    const int l = blockIdx.x, br = blockIdx.y;
    const float* Q = (br ? g_qW : g_qH) + (size_t)l * 4096;
    const float* K = (br ? g_kW : g_kH) + (size_t)l * 4096;
    float* E = (br ? g_EW : g_EH) + (size_t)l * 16384;
    const int t = threadIdx.x;

    #pragma unroll
    for (int r = 0; r < 4; r++) {
        int lin = t + r * 256;
        int p = lin >> 3, c4 = (lin & 7) << 2;
        float4 q = *(const float4*)(Q + (size_t)p * 32 + c4);
        Qt[c4][p] = q.x; Qt[c4 + 1][p] = q.y; Qt[c4 + 2][p] = q.z; Qt[c4 + 3][p] = q.w;
        float4 kk = *(const float4*)(K + (size_t)p * 32 + c4);
        Kt[c4][p] = kk.x; Kt[c4 + 1][p] = kk.y; Kt[c4 + 2][p] = kk.z; Kt[c4 + 3][p] = kk.w;
    }
    __syncthreads();

    const int tj = t & 15, ti = t >> 4;
    const int i0 = ti * 8, j0 = tj * 8;
    ull acc2[8][4];
    #pragma unroll
    for (int u = 0; u < 8; u++)
        #pragma unroll
        for (int v = 0; v < 4; v++) acc2[u][v] = 0ULL;

    #pragma unroll
    for (int c = 0; c < 32; c++) {
        float4 qa = *(const float4*)&Qt[c][i0];
        float4 qb = *(const float4*)&Qt[c][i0 + 4];
        ull ad[8] = {dup2(qa.x), dup2(qa.y), dup2(qa.z), dup2(qa.w),
                     dup2(qb.x), dup2(qb.y), dup2(qb.z), dup2(qb.w)};
        const ull* kp = (const ull*)&Kt[c][j0];
        ull b0 = kp[0], b1 = kp[1], b2 = kp[2], b3 = kp[3];
        #pragma unroll
        for (int u = 0; u < 8; u++) {
            ffma2(acc2[u][0], ad[u], b0);
            ffma2(acc2[u][1], ad[u], b1);
            ffma2(acc2[u][2], ad[u], b2);
            ffma2(acc2[u][3], ad[u], b3);
        }
    }
    #pragma unroll
    for (int u = 0; u < 8; u++) {
        float2 p0 = u2f(acc2[u][0]), p1 = u2f(acc2[u][1]);
        float2 p2 = u2f(acc2[u][2]), p3 = u2f(acc2[u][3]);
        *(float4*)(E + (size_t)(i0 + u) * 128 + j0)     = make_float4(p0.x, p0.y, p1.x, p1.y);
        *(float4*)(E + (size_t)(i0 + u) * 128 + j0 + 4) = make_float4(p2.x, p2.y, p3.x, p3.y);
    }
}

// ---- joint softmax: one warp per pixel, grid 8192 x 256 ----
__global__ void kern_softmax()
{
    int gw = (blockIdx.x * blockDim.x + threadIdx.x) >> 5;
    int lane = threadIdx.x & 31;
    if (gw >= 65536) return;
    int b = gw >> 14;
    int rem = gw & 16383;
    int h = rem >> 7, w = rem & 127;
    float* r1 = g_EH + (((size_t)(b * 128 + w)) * 128 + h) * 128;
    float* r2 = g_EW + (((size_t)(b * 128 + h)) * 128 + w) * 128;
    float4 a = *(float4*)(r1 + lane * 4);
    float4 c = *(float4*)(r2 + lane * 4);
    float e1[4] = {a.x, a.y, a.z, a.w};
    float e2[4] = {c.x, c.y, c.z, c.w};
    float m = -INFINITY;
    #pragma unroll
    for (int u = 0; u < 4; u++) {
        if (lane * 4 + u != h) m = fmaxf(m, e1[u]);
        m = fmaxf(m, e2[u]);
    }
    #pragma unroll
    for (int s = 16; s > 0; s >>= 1) m = fmaxf(m, __shfl_xor_sync(0xffffffffu, m, s));
    float sum = 0.f;
    #pragma unroll
    for (int u = 0; u < 4; u++) {
        e1[u] = (lane * 4 + u == h) ? 0.f : __expf(e1[u] - m);
        sum += e1[u];
        e2[u] = __expf(e2[u] - m);
        sum += e2[u];
    }
    #pragma unroll
    for (int s = 16; s > 0; s >>= 1) sum += __shfl_xor_sync(0xffffffffu, sum, s);
    float inv = 1.0f / sum;
    *(float4*)(r1 + lane * 4) = make_float4(e1[0] * inv, e1[1] * inv, e1[2] * inv, e1[3] * inv);
    *(float4*)(r2 + lane * 4) = make_float4(e2[0] * inv, e2[1] * inv, e2[2] * inv, e2[3] * inv);
}

// ---- per-line output GEMM O = A @ V, cp.async double-buffered ----
// grid (512, 2 chalf, 2 br), block 256
__global__ __launch_bounds__(256, 2) void kern_out()
{
    __shared__ __align__(16) float AsF[2 * 128 * 16];  // [2][k=128][hh=16]
    __shared__ __align__(16) float VsF[2 * 16 * 128];  // [2][hh=16][c=128]
    const int l = blockIdx.x, chf = blockIdx.y, br = blockIdx.z;
    const float* A = (br ? g_EW : g_EH) + (size_t)l * 16384;
    const float* V = (br ? g_vW : g_vH) + (size_t)l * 32768 + chf * 128;
    float* O = (br ? g_rO : g_cO) + (size_t)l * 32768 + chf * 128;
    const int t = threadIdx.x;
    const int tj = t & 15, ti = t >> 4;
    const int i0 = ti * 8, j0 = tj * 8;

    const unsigned as_u = (unsigned)__cvta_generic_to_shared(AsF);
    const unsigned vs_u = (unsigned)__cvta_generic_to_shared(VsF);

    ull acc2[8][4];
    #pragma unroll
    for (int u = 0; u < 8; u++)
        #pragma unroll
        for (int v = 0; v < 4; v++) acc2[u][v] = 0ULL;

    // prologue: hc=0
    {
        #pragma unroll
        for (int r = 0; r < 2; r++) {
            int lin = t + r * 256;
            int k = lin >> 2, h4 = (lin & 3) << 2;
            cpa16(as_u + (unsigned)((k * 16 + h4) * 4), A + (size_t)k * 128 + h4);
        }
        #pragma unroll
        for (int r = 0; r < 2; r++) {
            int lin = t + r * 256;
            int hh = lin >> 5, ch = (lin & 31) << 2;
            cpa16(vs_u + (unsigned)((hh * 128 + ch) * 4), V + (size_t)hh * 256 + ch);
        }
        cpa_commit();
    }

    for (int hc = 0; hc < 8; hc++) {
        const int buf = hc & 1;
        if (hc < 7) {
            const int nb = buf ^ 1, hn = hc + 1;
            #pragma unroll
            for (int r = 0; r < 2; r++) {
                int lin = t + r * 256;
                int k = lin >> 2, h4 = (lin & 3) << 2;
                cpa16(as_u + (unsigned)((nb * 2048 + k * 16 + h4) * 4),
                      A + (size_t)k * 128 + hn * 16 + h4);
            }
            #pragma unroll
            for (int r = 0; r < 2; r++) {
                int lin = t + r * 256;
                int hh = lin >> 5, ch = (lin & 31) << 2;
                cpa16(vs_u + (unsigned)((nb * 2048 + hh * 128 + ch) * 4),
                      V + (size_t)(hn * 16 + hh) * 256 + ch);
            }
            cpa_commit();
            cpa_wait<1>();
        } else {
            cpa_wait<0>();
        }
        __syncthreads();

        const float* Ab = AsF + buf * 2048;
        const float* Vb = VsF + buf * 2048;
        #pragma unroll
        for (int hh = 0; hh < 16; hh++) {
            ull ad[8];
            #pragma unroll
            for (int u = 0; u < 8; u++) ad[u] = dup2(Ab[(i0 + u) * 16 + hh]);
            const ull* vp = (const ull*)(Vb + hh * 128 + j0);
            ull b0 = vp[0], b1 = vp[1], b2 = vp[2], b3 = vp[3];
            #pragma unroll
            for (int u = 0; u < 8; u++) {
                ffma2(acc2[u][0], ad[u], b0);
                ffma2(acc2[u][1], ad[u], b1);
                ffma2(acc2[u][2], ad[u], b2);
                ffma2(acc2[u][3], ad[u], b3);
            }
        }
        __syncthreads();
    }

    #pragma unroll
    for (int u = 0; u < 8; u++) {
        float2 p0 = u2f(acc2[u][0]), p1 = u2f(acc2[u][1]);
        float2 p2 = u2f(acc2[u][2]), p3 = u2f(acc2[u][3]);
        *(float4*)(O + (size_t)(i0 + u) * 256 + j0)     = make_float4(p0.x, p0.y, p1.x, p1.y);
        *(float4*)(O + (size_t)(i0 + u) * 256 + j0 + 4) = make_float4(p2.x, p2.y, p3.x, p3.y);
    }
}

// ---- combine: out = gamma*(colO + rowO) + x: grid (128 h, 8 ctile, 4 b), block 256 ----
__global__ void kern_combine(const float* __restrict__ x, const float* __restrict__ gamma,
                             float* __restrict__ out)
{
    __shared__ __align__(16) float s[32][132];
    const int h = blockIdx.x, ct = blockIdx.y, b = blockIdx.z;
    const int c0 = ct * 32, t = threadIdx.x;
    #pragma unroll
    for (int r = 0; r < 4; r++) {
        int lin = t + r * 256;
        int w = lin >> 3, c4 = (lin & 7) << 2;
        float4 a = *(const float4*)(g_cO + (((size_t)(b * 128 + w)) * 128 + h) * 256 + c0 + c4);
        float4 bb = *(const float4*)(g_rO + (((size_t)(b * 128 + h)) * 128 + w) * 256 + c0 + c4);
        s[c4][w] = a.x + bb.x; s[c4 + 1][w] = a.y + bb.y;
        s[c4 + 2][w] = a.z + bb.z; s[c4 + 3][w] = a.w + bb.w;
    }
    __syncthreads();
    float g = gamma[0];
    #pragma unroll
    for (int r = 0; r < 4; r++) {
        int lin = t + r * 256;
        int c = lin >> 5, w4 = (lin & 31) << 2;
        size_t oidx = (((size_t)b * 256 + c0 + c) * 128 + h) * 128 + w4;
        float4 xv = *(const float4*)(x + oidx);
        float4 o;
        o.x = g * s[c][w4] + xv.x;
        o.y = g * s[c][w4 + 1] + xv.y;
        o.z = g * s[c][w4 + 2] + xv.z;
        o.w = g * s[c][w4 + 3] + xv.w;
        *(float4*)(out + oidx) = o;
    }
}

extern "C" void kernel_launch(void* const* d_in, const int* in_sizes, int n_in,
                              void* d_out, int out_size)
{
    const float* x      = (const float*)d_in[0];
    const float* Wq     = (const float*)d_in[1];
    const float* bq     = (const float*)d_in[2];
    const float* Wk     = (const float*)d_in[3];
    const float* bk     = (const float*)d_in[4];
    const float* Wv     = (const float*)d_in[5];
    const float* bv     = (const float*)d_in[6];
    const float* gamma  = (const float*)d_in[7];
    const float* offs   = (const float*)d_in[8];
    float* out = (float*)d_out;

    kern_prep<<<1, 512>>>(offs, out, out_size - 1);
    kern_wt<<<320, 256>>>(Wq, bq, Wk, bk, Wv, bv);
    kern_proj<<<dim3(5, 128, 4), 256>>>(x);
    kern_sample<<<dim3(16384, 2), 320>>>();
    kern_energy<<<dim3(512, 2), 256>>>();
    kern_softmax<<<8192, 256>>>();
    kern_out<<<dim3(512, 2, 2), 256>>>();
    kern_combine<<<dim3(128, 8, 4), 256>>>(x, gamma, out);
}

// round 7
// speedup vs baseline: 1.2173x; 1.2173x over previous
#include <cuda_runtime.h>
#include <math.h>

#define OFFD 131

__device__ float g_qH[512*128*32];
__device__ float g_kH[512*128*32];
__device__ float g_qW[512*128*32];
__device__ float g_kW[512*128*32];
__device__ float g_vH[512*128*256];
__device__ float g_vW[512*128*256];
__device__ float g_p0[128*128*320];
__device__ float g_EH[512*128*128];
__device__ float g_EW[512*128*128];
__device__ float g_cO[512*128*256];
__device__ float g_rO[512*128*256];
__device__ float g_dX[129][2];
__device__ float g_dY[129][2];
__device__ float g_Wt[256*320];   // transposed fused weight [c][o]
__device__ float g_bias[320];

typedef unsigned long long ull;

__device__ __forceinline__ void ffma2(ull& d, ull a, ull b) {
    asm("fma.rn.f32x2 %0, %1, %2, %0;" : "+l"(d) : "l"(a), "l"(b));
}
__device__ __forceinline__ ull dup2(float x) {
    ull r; asm("mov.b64 %0, {%1, %1};" : "=l"(r) : "f"(x)); return r;
}
__device__ __forceinline__ float2 u2f(ull v) {
    float2 f; asm("mov.b64 {%0, %1}, %2;" : "=f"(f.x), "=f"(f.y) : "l"(v)); return f;
}

// ---- offset pooling + regloss ----
__global__ void kern_prep(const float* __restrict__ off, float* __restrict__ out, int regIdx)
{
    const int t = threadIdx.x;
    const float inv9 = 1.0f / 9.0f;
    for (int idx = t; idx < 258; idx += 512) {
        int r = idx % 129, ch = idx / 129;
        const float* o = off + ch * OFFD * OFFD;
        float s = 0.f;
        #pragma unroll
        for (int i = 0; i < 3; i++)
            #pragma unroll
            for (int j = 0; j < 3; j++) s += o[(r + i) * OFFD + 64 + j];
        g_dX[r][ch] = s * inv9;
    }
    for (int idx = t; idx < 258; idx += 512) {
        int c = idx % 129, ch = idx / 129;
        const float* o = off + ch * OFFD * OFFD;
        float s = 0.f;
        #pragma unroll
        for (int i = 0; i < 3; i++)
            #pragma unroll
            for (int j = 0; j < 3; j++) s += o[(64 + i) * OFFD + c + j];
        g_dY[c][ch] = s * inv9;
    }
    float s1 = 0.f, s2 = 0.f;
    for (int i = t; i < OFFD * OFFD; i += 512) {
        float d = off[i] - off[OFFD * OFFD + i];
        s1 += d * d;
    }
    for (int i = t; i < 2 * 130 * OFFD; i += 512) {
        int ch = i / (130 * OFFD);
        int rem = i - ch * 130 * OFFD;
        int r = rem / OFFD, c = rem - r * OFFD;
        float d = off[ch * OFFD * OFFD + r * OFFD + c] - off[ch * OFFD * OFFD + (r + 1) * OFFD + c];
        s2 += d * d;
    }
    __shared__ float sh1[512], sh2[512];
    sh1[t] = s1; sh2[t] = s2;
    __syncthreads();
    for (int s = 256; s > 0; s >>= 1) {
        if (t < s) { sh1[t] += sh1[t + s]; sh2[t] += sh2[t + s]; }
        __syncthreads();
    }
    if (t == 0)
        out[regIdx] = sh1[0] / (float)(OFFD * OFFD) + sh2[0] / (float)(2 * 130 * OFFD);
}

// ---- weight transpose: g_Wt[c][o], g_bias[o] ----
__global__ void kern_wt(const float* __restrict__ Wq, const float* __restrict__ bq,
                        const float* __restrict__ Wk, const float* __restrict__ bk,
                        const float* __restrict__ Wv, const float* __restrict__ bv)
{
    const int o = blockIdx.x;
    const int c = threadIdx.x;
    const float* row = (o < 32) ? (Wq + (size_t)o * 256)
                      : (o < 64) ? (Wk + (size_t)(o - 32) * 256)
                                 : (Wv + (size_t)(o - 64) * 256);
    g_Wt[(size_t)c * 320 + o] = row[c];
    if (c == 0)
        g_bias[o] = (o < 32) ? bq[o] : (o < 64) ? bk[o - 32] : bv[o - 64];
}

// ---- fused QKV projection GEMM: grid (h=128, otile=5, b=4), block 256 ----
__global__ __launch_bounds__(256, 3) void kern_proj(const float* __restrict__ x)
{
    __shared__ __align__(16) float sm[8704];
    float (*Xs)[132] = (float (*)[132])sm;
    float (*Wt)[68]  = (float (*)[68])(sm + 32 * 132);
    float (*Ot)[68]  = (float (*)[68])sm;

    const int h = blockIdx.x, ot = blockIdx.y, b = blockIdx.z;
    const int t = threadIdx.x;
    const int tw = t & 15, to = t >> 4;
    const int o0 = ot * 64;

    ull acc2[4][4];
    #pragma unroll
    for (int j = 0; j < 4; j++)
        #pragma unroll
        for (int i = 0; i < 4; i++) acc2[j][i] = 0ULL;

    const float* xb = x + ((size_t)b * 256) * 16384 + (size_t)h * 128;

    for (int kc = 0; kc < 8; kc++) {
        const int c0 = kc * 32;
        #pragma unroll
        for (int r = 0; r < 4; r++) {
            int lin = t + r * 256;
            int row = lin >> 5, col = (lin & 31) << 2;
            *(float4*)&Xs[row][col] = *(const float4*)(xb + (size_t)(c0 + row) * 16384 + col);
        }
        {
            int row = t >> 4, o4 = (t & 15) << 2;  // 512 float4 over 2 rounds
            *(float4*)&Wt[row][o4] = *(const float4*)(g_Wt + (size_t)(c0 + row) * 320 + o0 + o4);
            row += 16;
            *(float4*)&Wt[row][o4] = *(const float4*)(g_Wt + (size_t)(c0 + row) * 320 + o0 + o4);
        }
        __syncthreads();
        #pragma unroll
        for (int cc = 0; cc < 32; cc++) {
            const ull* xp = (const ull*)&Xs[cc][tw * 8];
            ull x0 = xp[0], x1 = xp[1], x2 = xp[2], x3 = xp[3];
            float4 wv = *(const float4*)&Wt[cc][to * 4];
            ull wd[4] = {dup2(wv.x), dup2(wv.y), dup2(wv.z), dup2(wv.w)};
            #pragma unroll
            for (int j = 0; j < 4; j++) {
                ffma2(acc2[j][0], wd[j], x0);
                ffma2(acc2[j][1], wd[j], x1);
                ffma2(acc2[j][2], wd[j], x2);
                ffma2(acc2[j][3], wd[j], x3);
            }
        }
        __syncthreads();
    }

    #pragma unroll
    for (int j = 0; j < 4; j++) {
        float bs = g_bias[o0 + to * 4 + j];
        #pragma unroll
        for (int i2 = 0; i2 < 4; i2++) {
            float2 f = u2f(acc2[j][i2]);
            Ot[tw * 8 + 2 * i2][to * 4 + j]     = f.x + bs;
            Ot[tw * 8 + 2 * i2 + 1][to * 4 + j] = f.y + bs;
        }
    }
    __syncthreads();

    if (ot == 0) {
        int w = t >> 1, half = t & 1;
        const float* src = &Ot[w][half * 32];
        if (b > 0) {
            float* dst = half ? (g_kH + (((size_t)(b * 128 + w)) * 128 + h) * 32)
                              : (g_qH + (((size_t)(b * 128 + w)) * 128 + h) * 32);
            #pragma unroll
            for (int i = 0; i < 8; i++) ((float4*)dst)[i] = ((const float4*)src)[i];
            float* dq = g_qW + ((size_t)(b * 128 + h)) * 4096;
            float* dk = g_kW + ((size_t)(b * 128 + h)) * 4096;
            #pragma unroll
            for (int r = 0; r < 4; r++) {
                int e = (t + r * 256) << 2;
                int wI = e >> 5, cI = e & 31;
                *(float4*)(dq + e) = *(const float4*)&Ot[wI][cI];
                *(float4*)(dk + e) = *(const float4*)&Ot[wI][32 + cI];
            }
        } else {
            float* dst = g_p0 + ((size_t)(h * 128 + w)) * 320 + half * 32;
            #pragma unroll
            for (int i = 0; i < 8; i++) ((float4*)dst)[i] = ((const float4*)src)[i];
        }
    } else {
        const int c0v = (ot - 1) * 64;
        int w = t >> 1, half = t & 1;
        const float* src = &Ot[w][half * 32];
        if (b > 0) {
            float* dst = g_vH + (((size_t)(b * 128 + w)) * 128 + h) * 256 + c0v + half * 32;
            #pragma unroll
            for (int i = 0; i < 8; i++) ((float4*)dst)[i] = ((const float4*)src)[i];
            float* dw = g_vW + ((size_t)(b * 128 + h)) * 32768 + c0v;
            #pragma unroll
            for (int r = 0; r < 8; r++) {
                int e = (t + r * 256) << 2;
                int wI = e >> 6, cI = e & 63;
                *(float4*)(dw + (size_t)wI * 256 + cI) = *(const float4*)&Ot[wI][cI];
            }
        } else {
            float* dst = g_p0 + ((size_t)(h * 128 + w)) * 320 + 64 + c0v + half * 32;
            #pragma unroll
            for (int i = 0; i < 8; i++) ((float4*)dst)[i] = ((const float4*)src)[i];
        }
    }
}

// ---- deformable bilinear sampling of batch-0 lines: grid (16384, 2), block 320 ----
__global__ void kern_sample()
{
    const int pt = blockIdx.x, br = blockIdx.y;
    const int k = pt >> 7, pos = pt & 127;
    float px, py;
    if (br == 0) {
        int r = pos + 1;
        px = (-1.0f + k * 0.015625f) + g_dX[r][0];
        py = (-1.0f + r * 0.015625f) + g_dX[r][1];
    } else {
        int ci = pos + 1;
        px = (-1.0f + ci * 0.015625f) + g_dY[ci][0];
        py = (-1.0f + k * 0.015625f) + g_dY[ci][1];
    }
    float fx = (px + 1.0f) * 0.5f * 127.0f;
    float fy = (py + 1.0f) * 0.5f * 127.0f;
    float x0f = floorf(fx), y0f = floorf(fy);
    float wx = fx - x0f, wy = fy - y0f;
    int x0 = (int)x0f, y0 = (int)y0f;
    bool vx0 = (x0 >= 0) && (x0 < 128);
    bool vx1 = (x0 + 1 >= 0) && (x0 + 1 < 128);
    bool vy0 = (y0 >= 0) && (y0 < 128);
    bool vy1 = (y0 + 1 >= 0) && (y0 + 1 < 128);

    const int c = threadIdx.x;
    float acc = 0.f;
    if (vx0 && vy0) acc += g_p0[((size_t)(y0 * 128 + x0)) * 320 + c] * ((1.f - wx) * (1.f - wy));
    if (vx1 && vy0) acc += g_p0[((size_t)(y0 * 128 + x0 + 1)) * 320 + c] * (wx * (1.f - wy));
    if (vx0 && vy1) acc += g_p0[((size_t)((y0 + 1) * 128 + x0)) * 320 + c] * ((1.f - wx) * wy);
    if (vx1 && vy1) acc += g_p0[((size_t)((y0 + 1) * 128 + x0 + 1)) * 320 + c] * (wx * wy);

    size_t lp = (size_t)k * 128 + pos;
    if (br == 0) {
        if (c < 32)      g_qH[lp * 32 + c] = acc;
        else if (c < 64) g_kH[lp * 32 + (c - 32)] = acc;
        else             g_vH[lp * 256 + (c - 64)] = acc;
    } else {
        if (c < 32)      g_qW[lp * 32 + c] = acc;
        else if (c < 64) g_kW[lp * 32 + (c - 32)] = acc;
        else             g_vW[lp * 256 + (c - 64)] = acc;
    }
}

// ---- per-line energy GEMM E = Q @ K^T: grid (512, 2), block 256 ----
__global__ __launch_bounds__(256, 3) void kern_energy()
{
    __shared__ __align__(16) float Qt[32][132];
    __shared__ __align__(16) float Kt[32][132];
    const int l = blockIdx.x, br = blockIdx.y;
    const float* Q = (br ? g_qW : g_qH) + (size_t)l * 4096;
    const float* K = (br ? g_kW : g_kH) + (size_t)l * 4096;
    float* E = (br ? g_EW : g_EH) + (size_t)l * 16384;
    const int t = threadIdx.x;

    #pragma unroll
    for (int r = 0; r < 4; r++) {
        int lin = t + r * 256;
        int p = lin >> 3, c4 = (lin & 7) << 2;
        float4 q = *(const float4*)(Q + (size_t)p * 32 + c4);
        Qt[c4][p] = q.x; Qt[c4 + 1][p] = q.y; Qt[c4 + 2][p] = q.z; Qt[c4 + 3][p] = q.w;
        float4 kk = *(const float4*)(K + (size_t)p * 32 + c4);
        Kt[c4][p] = kk.x; Kt[c4 + 1][p] = kk.y; Kt[c4 + 2][p] = kk.z; Kt[c4 + 3][p] = kk.w;
    }
    __syncthreads();

    const int tj = t & 15, ti = t >> 4;
    const int i0 = ti * 8, j0 = tj * 8;
    ull acc2[8][4];
    #pragma unroll
    for (int u = 0; u < 8; u++)
        #pragma unroll
        for (int v = 0; v < 4; v++) acc2[u][v] = 0ULL;

    #pragma unroll
    for (int c = 0; c < 32; c++) {
        float4 qa = *(const float4*)&Qt[c][i0];
        float4 qb = *(const float4*)&Qt[c][i0 + 4];
        ull ad[8] = {dup2(qa.x), dup2(qa.y), dup2(qa.z), dup2(qa.w),
                     dup2(qb.x), dup2(qb.y), dup2(qb.z), dup2(qb.w)};
        const ull* kp = (const ull*)&Kt[c][j0];
        ull b0 = kp[0], b1 = kp[1], b2 = kp[2], b3 = kp[3];
        #pragma unroll
        for (int u = 0; u < 8; u++) {
            ffma2(acc2[u][0], ad[u], b0);
            ffma2(acc2[u][1], ad[u], b1);
            ffma2(acc2[u][2], ad[u], b2);
            ffma2(acc2[u][3], ad[u], b3);
        }
    }
    #pragma unroll
    for (int u = 0; u < 8; u++) {
        float2 p0 = u2f(acc2[u][0]), p1 = u2f(acc2[u][1]);
        float2 p2 = u2f(acc2[u][2]), p3 = u2f(acc2[u][3]);
        *(float4*)(E + (size_t)(i0 + u) * 128 + j0)     = make_float4(p0.x, p0.y, p1.x, p1.y);
        *(float4*)(E + (size_t)(i0 + u) * 128 + j0 + 4) = make_float4(p2.x, p2.y, p3.x, p3.y);
    }
}

// ---- joint softmax: one warp per pixel, grid 8192 x 256 ----
__global__ void kern_softmax()
{
    int gw = (blockIdx.x * blockDim.x + threadIdx.x) >> 5;
    int lane = threadIdx.x & 31;
    if (gw >= 65536) return;
    int b = gw >> 14;
    int rem = gw & 16383;
    int h = rem >> 7, w = rem & 127;
    float* r1 = g_EH + (((size_t)(b * 128 + w)) * 128 + h) * 128;
    float* r2 = g_EW + (((size_t)(b * 128 + h)) * 128 + w) * 128;
    float4 a = *(float4*)(r1 + lane * 4);
    float4 c = *(float4*)(r2 + lane * 4);
    float e1[4] = {a.x, a.y, a.z, a.w};
    float e2[4] = {c.x, c.y, c.z, c.w};
    float m = -INFINITY;
    #pragma unroll
    for (int u = 0; u < 4; u++) {
        if (lane * 4 + u != h) m = fmaxf(m, e1[u]);
        m = fmaxf(m, e2[u]);
    }
    #pragma unroll
    for (int s = 16; s > 0; s >>= 1) m = fmaxf(m, __shfl_xor_sync(0xffffffffu, m, s));
    float sum = 0.f;
    #pragma unroll
    for (int u = 0; u < 4; u++) {
        e1[u] = (lane * 4 + u == h) ? 0.f : __expf(e1[u] - m);
        sum += e1[u];
        e2[u] = __expf(e2[u] - m);
        sum += e2[u];
    }
    #pragma unroll
    for (int s = 16; s > 0; s >>= 1) sum += __shfl_xor_sync(0xffffffffu, sum, s);
    float inv = 1.0f / sum;
    *(float4*)(r1 + lane * 4) = make_float4(e1[0] * inv, e1[1] * inv, e1[2] * inv, e1[3] * inv);
    *(float4*)(r2 + lane * 4) = make_float4(e2[0] * inv, e2[1] * inv, e2[2] * inv, e2[3] * inv);
}

// ---- per-line output GEMM O = A @ V: grid (512, 2 chalf, 2 br), block 256 ----
__global__ __launch_bounds__(256, 3) void kern_out()
{
    __shared__ __align__(16) float As[32][132];
    __shared__ __align__(16) float Vs[32][132];
    const int l = blockIdx.x, chf = blockIdx.y, br = blockIdx.z;
    const float* A = (br ? g_EW : g_EH) + (size_t)l * 16384;
    const float* V = (br ? g_vW : g_vH) + (size_t)l * 32768;
    float* O = (br ? g_rO : g_cO) + (size_t)l * 32768 + chf * 128;
    const int t = threadIdx.x;
    const int tj = t & 15, ti = t >> 4;
    const int i0 = ti * 8, j0 = tj * 8;

    ull acc2[8][4];
    #pragma unroll
    for (int u = 0; u < 8; u++)
        #pragma unroll
        for (int v = 0; v < 4; v++) acc2[u][v] = 0ULL;

    for (int hc = 0; hc < 4; hc++) {
        #pragma unroll
        for (int r = 0; r < 4; r++) {
            int lin = t + r * 256;
            int k = lin >> 3, h4 = (lin & 7) << 2;
            float4 a = *(const float4*)(A + (size_t)k * 128 + hc * 32 + h4);
            As[h4][k] = a.x; As[h4 + 1][k] = a.y; As[h4 + 2][k] = a.z; As[h4 + 3][k] = a.w;
            int hh = lin >> 5, c4 = (lin & 31) << 2;
            *(float4*)&Vs[hh][c4] = *(const float4*)(V + (size_t)(hc * 32 + hh) * 256 + chf * 128 + c4);
        }
        __syncthreads();
        #pragma unroll
        for (int hh = 0; hh < 32; hh++) {
            float4 aa = *(const float4*)&As[hh][i0];
            float4 ab = *(const float4*)&As[hh][i0 + 4];
            ull ad[8] = {dup2(aa.x), dup2(aa.y), dup2(aa.z), dup2(aa.w),
                         dup2(ab.x), dup2(ab.y), dup2(ab.z), dup2(ab.w)};
            const ull* vp = (const ull*)&Vs[hh][j0];
            ull b0 = vp[0], b1 = vp[1], b2 = vp[2], b3 = vp[3];
            #pragma unroll
            for (int u = 0; u < 8; u++) {
                ffma2(acc2[u][0], ad[u], b0);
                ffma2(acc2[u][1], ad[u], b1);
                ffma2(acc2[u][2], ad[u], b2);
                ffma2(acc2[u][3], ad[u], b3);
            }
        }
        __syncthreads();
    }
    #pragma unroll
    for (int u = 0; u < 8; u++) {
        float2 p0 = u2f(acc2[u][0]), p1 = u2f(acc2[u][1]);
        float2 p2 = u2f(acc2[u][2]), p3 = u2f(acc2[u][3]);
        *(float4*)(O + (size_t)(i0 + u) * 256 + j0)     = make_float4(p0.x, p0.y, p1.x, p1.y);
        *(float4*)(O + (size_t)(i0 + u) * 256 + j0 + 4) = make_float4(p2.x, p2.y, p3.x, p3.y);
    }
}

// ---- combine: out = gamma*(colO + rowO) + x: grid (128 h, 8 ctile, 4 b), block 256 ----
__global__ void kern_combine(const float* __restrict__ x, const float* __restrict__ gamma,
                             float* __restrict__ out)
{
    __shared__ __align__(16) float s[32][132];
    const int h = blockIdx.x, ct = blockIdx.y, b = blockIdx.z;
    const int c0 = ct * 32, t = threadIdx.x;
    #pragma unroll
    for (int r = 0; r < 4; r++) {
        int lin = t + r * 256;
        int w = lin >> 3, c4 = (lin & 7) << 2;
        float4 a = *(const float4*)(g_cO + (((size_t)(b * 128 + w)) * 128 + h) * 256 + c0 + c4);
        float4 bb = *(const float4*)(g_rO + (((size_t)(b * 128 + h)) * 128 + w) * 256 + c0 + c4);
        s[c4][w] = a.x + bb.x; s[c4 + 1][w] = a.y + bb.y;
        s[c4 + 2][w] = a.z + bb.z; s[c4 + 3][w] = a.w + bb.w;
    }
    __syncthreads();
    float g = gamma[0];
    #pragma unroll
    for (int r = 0; r < 4; r++) {
        int lin = t + r * 256;
        int c = lin >> 5, w4 = (lin & 31) << 2;
        size_t oidx = (((size_t)b * 256 + c0 + c) * 128 + h) * 128 + w4;
        float4 xv = *(const float4*)(x + oidx);
        float4 o;
        o.x = g * s[c][w4] + xv.x;
        o.y = g * s[c][w4 + 1] + xv.y;
        o.z = g * s[c][w4 + 2] + xv.z;
        o.w = g * s[c][w4 + 3] + xv.w;
        *(float4*)(out + oidx) = o;
    }
}

extern "C" void kernel_launch(void* const* d_in, const int* in_sizes, int n_in,
                              void* d_out, int out_size)
{
    const float* x      = (const float*)d_in[0];
    const float* Wq     = (const float*)d_in[1];
    const float* bq     = (const float*)d_in[2];
    const float* Wk     = (const float*)d_in[3];
    const float* bk     = (const float*)d_in[4];
    const float* Wv     = (const float*)d_in[5];
    const float* bv     = (const float*)d_in[6];
    const float* gamma  = (const float*)d_in[7];
    const float* offs   = (const float*)d_in[8];
    float* out = (float*)d_out;

    kern_prep<<<1, 512>>>(offs, out, out_size - 1);
    kern_wt<<<320, 256>>>(Wq, bq, Wk, bk, Wv, bv);
    kern_proj<<<dim3(128, 5, 4), 256>>>(x);
    kern_sample<<<dim3(16384, 2), 320>>>();
    kern_energy<<<dim3(512, 2), 256>>>();
    kern_softmax<<<8192, 256>>>();
    kern_out<<<dim3(512, 2, 2), 256>>>();
    kern_combine<<<dim3(128, 8, 4), 256>>>(x, gamma, out);
}

// round 8
// speedup vs baseline: 1.5399x; 1.2650x over previous
#include <cuda_runtime.h>
#include <math.h>

#define OFFD 131

__device__ float g_qH[512*128*32];
__device__ float g_kH[512*128*32];
__device__ float g_qW[512*128*32];
__device__ float g_kW[512*128*32];
__device__ float g_vH[512*128*256];
__device__ float g_vW[512*128*256];
__device__ float g_p0[128*128*320];
__device__ float g_EH[512*128*128];
__device__ float g_EW[512*128*128];
__device__ float g_cO[512*128*256];
__device__ float g_rO[512*128*256];
__device__ float g_dX[129][2];
__device__ float g_dY[129][2];
__device__ float g_Wt[256*320];   // transposed fused weight [c][o]
__device__ float g_bias[320];

typedef unsigned long long ull;

__device__ __forceinline__ void ffma2(ull& d, ull a, ull b) {
    asm("fma.rn.f32x2 %0, %1, %2, %0;" : "+l"(d) : "l"(a), "l"(b));
}
__device__ __forceinline__ ull dup2(float x) {
    ull r; asm("mov.b64 %0, {%1, %1};" : "=l"(r) : "f"(x)); return r;
}
__device__ __forceinline__ float2 u2f(ull v) {
    float2 f; asm("mov.b64 {%0, %1}, %2;" : "=f"(f.x), "=f"(f.y) : "l"(v)); return f;
}
__device__ __forceinline__ void cpa16(unsigned dst, const float* src) {
    asm volatile("cp.async.ca.shared.global [%0], [%1], 16;" :: "r"(dst), "l"(src));
}
__device__ __forceinline__ void cpa_commit() {
    asm volatile("cp.async.commit_group;");
}
template<int N> __device__ __forceinline__ void cpa_wait() {
    asm volatile("cp.async.wait_group %0;" :: "n"(N));
}

// ---- offset pooling + regloss ----
__global__ void kern_prep(const float* __restrict__ off, float* __restrict__ out, int regIdx)
{
    const int t = threadIdx.x;
    const float inv9 = 1.0f / 9.0f;
    for (int idx = t; idx < 258; idx += 512) {
        int r = idx % 129, ch = idx / 129;
        const float* o = off + ch * OFFD * OFFD;
        float s = 0.f;
        #pragma unroll
        for (int i = 0; i < 3; i++)
            #pragma unroll
            for (int j = 0; j < 3; j++) s += o[(r + i) * OFFD + 64 + j];
        g_dX[r][ch] = s * inv9;
    }
    for (int idx = t; idx < 258; idx += 512) {
        int c = idx % 129, ch = idx / 129;
        const float* o = off + ch * OFFD * OFFD;
        float s = 0.f;
        #pragma unroll
        for (int i = 0; i < 3; i++)
            #pragma unroll
            for (int j = 0; j < 3; j++) s += o[(64 + i) * OFFD + c + j];
        g_dY[c][ch] = s * inv9;
    }
    float s1 = 0.f, s2 = 0.f;
    for (int i = t; i < OFFD * OFFD; i += 512) {
        float d = off[i] - off[OFFD * OFFD + i];
        s1 += d * d;
    }
    for (int i = t; i < 2 * 130 * OFFD; i += 512) {
        int ch = i / (130 * OFFD);
        int rem = i - ch * 130 * OFFD;
        int r = rem / OFFD, c = rem - r * OFFD;
        float d = off[ch * OFFD * OFFD + r * OFFD + c] - off[ch * OFFD * OFFD + (r + 1) * OFFD + c];
        s2 += d * d;
    }
    __shared__ float sh1[512], sh2[512];
    sh1[t] = s1; sh2[t] = s2;
    __syncthreads();
    for (int s = 256; s > 0; s >>= 1) {
        if (t < s) { sh1[t] += sh1[t + s]; sh2[t] += sh2[t + s]; }
        __syncthreads();
    }
    if (t == 0)
        out[regIdx] = sh1[0] / (float)(OFFD * OFFD) + sh2[0] / (float)(2 * 130 * OFFD);
}

// ---- weight transpose: g_Wt[c][o], g_bias[o] ----
__global__ void kern_wt(const float* __restrict__ Wq, const float* __restrict__ bq,
                        const float* __restrict__ Wk, const float* __restrict__ bk,
                        const float* __restrict__ Wv, const float* __restrict__ bv)
{
    const int o = blockIdx.x;
    const int c = threadIdx.x;
    const float* row = (o < 32) ? (Wq + (size_t)o * 256)
                      : (o < 64) ? (Wk + (size_t)(o - 32) * 256)
                                 : (Wv + (size_t)(o - 64) * 256);
    g_Wt[(size_t)c * 320 + o] = row[c];
    if (c == 0)
        g_bias[o] = (o < 32) ? bq[o] : (o < 64) ? bk[o - 32] : bv[o - 64];
}

// ---- fused QKV projection GEMM, cp.async.ca double-buffered ----
// grid (h=128, otile=5, b=4), block 256
__global__ __launch_bounds__(256) void kern_proj(const float* __restrict__ x)
{
    __shared__ __align__(16) float Xs[2][32][128];  // 32 KB
    __shared__ __align__(16) float Ws[2][32][64];   // 16 KB  (total 48 KB)
    float (*Ot)[68] = (float (*)[68])&Xs[0][0][0];

    const int h = blockIdx.x, ot = blockIdx.y, b = blockIdx.z;
    const int t = threadIdx.x;
    const int tw = t & 15, to = t >> 4;
    const int o0 = ot * 64;
    const float* xb = x + ((size_t)b * 256) * 16384 + (size_t)h * 128;

    const unsigned xs_u = (unsigned)__cvta_generic_to_shared(&Xs[0][0][0]);
    const unsigned ws_u = (unsigned)__cvta_generic_to_shared(&Ws[0][0][0]);

    ull acc2[4][4];
    #pragma unroll
    for (int j = 0; j < 4; j++)
        #pragma unroll
        for (int i = 0; i < 4; i++) acc2[j][i] = 0ULL;

    // prologue: tile kc=0 -> buf 0
    {
        #pragma unroll
        for (int r = 0; r < 4; r++) {
            int lin = t + r * 256;
            int row = lin >> 5, col = (lin & 31) << 2;
            cpa16(xs_u + (unsigned)((row * 128 + col) * 4), xb + (size_t)row * 16384 + col);
        }
        #pragma unroll
        for (int r = 0; r < 2; r++) {
            int lin = t + r * 256;
            int row = lin >> 4, o4 = (lin & 15) << 2;
            cpa16(ws_u + (unsigned)((row * 64 + o4) * 4), g_Wt + (size_t)row * 320 + o0 + o4);
        }
        cpa_commit();
    }

    for (int kc = 0; kc < 8; kc++) {
        const int buf = kc & 1;
        cpa_wait<0>();
        __syncthreads();           // tile kc visible; buf^1 free (everyone done reading it)
        if (kc < 7) {              // prefetch kc+1 into buf^1, overlapping compute(kc)
            const int nb = buf ^ 1, kn = kc + 1;
            #pragma unroll
            for (int r = 0; r < 4; r++) {
                int lin = t + r * 256;
                int row = lin >> 5, col = (lin & 31) << 2;
                cpa16(xs_u + (unsigned)((nb * 4096 + row * 128 + col) * 4),
                      xb + (size_t)(kn * 32 + row) * 16384 + col);
            }
            #pragma unroll
            for (int r = 0; r < 2; r++) {
                int lin = t + r * 256;
                int row = lin >> 4, o4 = (lin & 15) << 2;
                cpa16(ws_u + (unsigned)((nb * 2048 + row * 64 + o4) * 4),
                      g_Wt + (size_t)(kn * 32 + row) * 320 + o0 + o4);
            }
            cpa_commit();
        }
        const float* Xb = &Xs[buf][0][0];
        const float* Wb = &Ws[buf][0][0];
        #pragma unroll
        for (int cc = 0; cc < 32; cc++) {
            const ull* xp = (const ull*)(Xb + cc * 128 + tw * 8);
            ull x0 = xp[0], x1 = xp[1], x2 = xp[2], x3 = xp[3];
            float4 wv = *(const float4*)(Wb + cc * 64 + to * 4);
            ull wd[4] = {dup2(wv.x), dup2(wv.y), dup2(wv.z), dup2(wv.w)};
            #pragma unroll
            for (int j = 0; j < 4; j++) {
                ffma2(acc2[j][0], wd[j], x0);
                ffma2(acc2[j][1], wd[j], x1);
                ffma2(acc2[j][2], wd[j], x2);
                ffma2(acc2[j][3], wd[j], x3);
            }
        }
    }
    __syncthreads();   // all compute done before aliasing Ot over the buffers

    #pragma unroll
    for (int j = 0; j < 4; j++) {
        float bs = g_bias[o0 + to * 4 + j];
        #pragma unroll
        for (int i2 = 0; i2 < 4; i2++) {
            float2 f = u2f(acc2[j][i2]);
            Ot[tw * 8 + 2 * i2][to * 4 + j]     = f.x + bs;
            Ot[tw * 8 + 2 * i2 + 1][to * 4 + j] = f.y + bs;
        }
    }
    __syncthreads();

    if (ot == 0) {
        int w = t >> 1, half = t & 1;
        const float* src = &Ot[w][half * 32];
        if (b > 0) {
            float* dst = half ? (g_kH + (((size_t)(b * 128 + w)) * 128 + h) * 32)
                              : (g_qH + (((size_t)(b * 128 + w)) * 128 + h) * 32);
            #pragma unroll
            for (int i = 0; i < 8; i++) ((float4*)dst)[i] = ((const float4*)src)[i];
            float* dq = g_qW + ((size_t)(b * 128 + h)) * 4096;
            float* dk = g_kW + ((size_t)(b * 128 + h)) * 4096;
            #pragma unroll
            for (int r = 0; r < 4; r++) {
                int e = (t + r * 256) << 2;
                int wI = e >> 5, cI = e & 31;
                *(float4*)(dq + e) = *(const float4*)&Ot[wI][cI];
                *(float4*)(dk + e) = *(const float4*)&Ot[wI][32 + cI];
            }
        } else {
            float* dst = g_p0 + ((size_t)(h * 128 + w)) * 320 + half * 32;
            #pragma unroll
            for (int i = 0; i < 8; i++) ((float4*)dst)[i] = ((const float4*)src)[i];
        }
    } else {
        const int c0v = (ot - 1) * 64;
        int w = t >> 1, half = t & 1;
        const float* src = &Ot[w][half * 32];
        if (b > 0) {
            float* dst = g_vH + (((size_t)(b * 128 + w)) * 128 + h) * 256 + c0v + half * 32;
            #pragma unroll
            for (int i = 0; i < 8; i++) ((float4*)dst)[i] = ((const float4*)src)[i];
            float* dw = g_vW + ((size_t)(b * 128 + h)) * 32768 + c0v;
            #pragma unroll
            for (int r = 0; r < 8; r++) {
                int e = (t + r * 256) << 2;
                int wI = e >> 6, cI = e & 63;
                *(float4*)(dw + (size_t)wI * 256 + cI) = *(const float4*)&Ot[wI][cI];
            }
        } else {
            float* dst = g_p0 + ((size_t)(h * 128 + w)) * 320 + 64 + c0v + half * 32;
            #pragma unroll
            for (int i = 0; i < 8; i++) ((float4*)dst)[i] = ((const float4*)src)[i];
        }
    }
}

// ---- deformable bilinear sampling of batch-0 lines: grid (16384, 2), block 320 ----
__global__ void kern_sample()
{
    const int pt = blockIdx.x, br = blockIdx.y;
    const int k = pt >> 7, pos = pt & 127;
    float px, py;
    if (br == 0) {
        int r = pos + 1;
        px = (-1.0f + k * 0.015625f) + g_dX[r][0];
        py = (-1.0f + r * 0.015625f) + g_dX[r][1];
    } else {
        int ci = pos + 1;
        px = (-1.0f + ci * 0.015625f) + g_dY[ci][0];
        py = (-1.0f + k * 0.015625f) + g_dY[ci][1];
    }
    float fx = (px + 1.0f) * 0.5f * 127.0f;
    float fy = (py + 1.0f) * 0.5f * 127.0f;
    float x0f = floorf(fx), y0f = floorf(fy);
    float wx = fx - x0f, wy = fy - y0f;
    int x0 = (int)x0f, y0 = (int)y0f;
    bool vx0 = (x0 >= 0) && (x0 < 128);
    bool vx1 = (x0 + 1 >= 0) && (x0 + 1 < 128);
    bool vy0 = (y0 >= 0) && (y0 < 128);
    bool vy1 = (y0 + 1 >= 0) && (y0 + 1 < 128);

    const int c = threadIdx.x;
    float acc = 0.f;
    if (vx0 && vy0) acc += g_p0[((size_t)(y0 * 128 + x0)) * 320 + c] * ((1.f - wx) * (1.f - wy));
    if (vx1 && vy0) acc += g_p0[((size_t)(y0 * 128 + x0 + 1)) * 320 + c] * (wx * (1.f - wy));
    if (vx0 && vy1) acc += g_p0[((size_t)((y0 + 1) * 128 + x0)) * 320 + c] * ((1.f - wx) * wy);
    if (vx1 && vy1) acc += g_p0[((size_t)((y0 + 1) * 128 + x0 + 1)) * 320 + c] * (wx * wy);

    size_t lp = (size_t)k * 128 + pos;
    if (br == 0) {
        if (c < 32)      g_qH[lp * 32 + c] = acc;
        else if (c < 64) g_kH[lp * 32 + (c - 32)] = acc;
        else             g_vH[lp * 256 + (c - 64)] = acc;
    } else {
        if (c < 32)      g_qW[lp * 32 + c] = acc;
        else if (c < 64) g_kW[lp * 32 + (c - 32)] = acc;
        else             g_vW[lp * 256 + (c - 64)] = acc;
    }
}

// ---- per-line energy GEMM E = Q @ K^T: grid (512, 2), block 256 ----
__global__ __launch_bounds__(256) void kern_energy()
{
    __shared__ __align__(16) float Qt[32][132];
    __shared__ __align__(16) float Kt[32][132];
    const int l = blockIdx.x, br = blockIdx.y;
    const float* Q = (br ? g_qW : g_qH) + (size_t)l * 4096;
    const float* K = (br ? g_kW : g_kH) + (size_t)l * 4096;
    float* E = (br ? g_EW : g_EH) + (size_t)l * 16384;
    const int t = threadIdx.x;

    #pragma unroll
    for (int r = 0; r < 4; r++) {
        int lin = t + r * 256;
        int p = lin >> 3, c4 = (lin & 7) << 2;
        float4 q = *(const float4*)(Q + (size_t)p * 32 + c4);
        Qt[c4][p] = q.x; Qt[c4 + 1][p] = q.y; Qt[c4 + 2][p] = q.z; Qt[c4 + 3][p] = q.w;
        float4 kk = *(const float4*)(K + (size_t)p * 32 + c4);
        Kt[c4][p] = kk.x; Kt[c4 + 1][p] = kk.y; Kt[c4 + 2][p] = kk.z; Kt[c4 + 3][p] = kk.w;
    }
    __syncthreads();

    const int tj = t & 15, ti = t >> 4;
    const int i0 = ti * 8, j0 = tj * 8;
    ull acc2[8][4];
    #pragma unroll
    for (int u = 0; u < 8; u++)
        #pragma unroll
        for (int v = 0; v < 4; v++) acc2[u][v] = 0ULL;

    #pragma unroll
    for (int c = 0; c < 32; c++) {
        float4 qa = *(const float4*)&Qt[c][i0];
        float4 qb = *(const float4*)&Qt[c][i0 + 4];
        ull ad[8] = {dup2(qa.x), dup2(qa.y), dup2(qa.z), dup2(qa.w),
                     dup2(qb.x), dup2(qb.y), dup2(qb.z), dup2(qb.w)};
        const ull* kp = (const ull*)&Kt[c][j0];
        ull b0 = kp[0], b1 = kp[1], b2 = kp[2], b3 = kp[3];
        #pragma unroll
        for (int u = 0; u < 8; u++) {
            ffma2(acc2[u][0], ad[u], b0);
            ffma2(acc2[u][1], ad[u], b1);
            ffma2(acc2[u][2], ad[u], b2);
            ffma2(acc2[u][3], ad[u], b3);
        }
    }
    #pragma unroll
    for (int u = 0; u < 8; u++) {
        float2 p0 = u2f(acc2[u][0]), p1 = u2f(acc2[u][1]);
        float2 p2 = u2f(acc2[u][2]), p3 = u2f(acc2[u][3]);
        *(float4*)(E + (size_t)(i0 + u) * 128 + j0)     = make_float4(p0.x, p0.y, p1.x, p1.y);
        *(float4*)(E + (size_t)(i0 + u) * 128 + j0 + 4) = make_float4(p2.x, p2.y, p3.x, p3.y);
    }
}

// ---- joint softmax: one warp per pixel, grid 8192 x 256 ----
__global__ void kern_softmax()
{
    int gw = (blockIdx.x * blockDim.x + threadIdx.x) >> 5;
    int lane = threadIdx.x & 31;
    if (gw >= 65536) return;
    int b = gw >> 14;
    int rem = gw & 16383;
    int h = rem >> 7, w = rem & 127;
    float* r1 = g_EH + (((size_t)(b * 128 + w)) * 128 + h) * 128;
    float* r2 = g_EW + (((size_t)(b * 128 + h)) * 128 + w) * 128;
    float4 a = *(float4*)(r1 + lane * 4);
    float4 c = *(float4*)(r2 + lane * 4);
    float e1[4] = {a.x, a.y, a.z, a.w};
    float e2[4] = {c.x, c.y, c.z, c.w};
    float m = -INFINITY;
    #pragma unroll
    for (int u = 0; u < 4; u++) {
        if (lane * 4 + u != h) m = fmaxf(m, e1[u]);
        m = fmaxf(m, e2[u]);
    }
    #pragma unroll
    for (int s = 16; s > 0; s >>= 1) m = fmaxf(m, __shfl_xor_sync(0xffffffffu, m, s));
    float sum = 0.f;
    #pragma unroll
    for (int u = 0; u < 4; u++) {
        e1[u] = (lane * 4 + u == h) ? 0.f : __expf(e1[u] - m);
        sum += e1[u];
        e2[u] = __expf(e2[u] - m);
        sum += e2[u];
    }
    #pragma unroll
    for (int s = 16; s > 0; s >>= 1) sum += __shfl_xor_sync(0xffffffffu, sum, s);
    float inv = 1.0f / sum;
    *(float4*)(r1 + lane * 4) = make_float4(e1[0] * inv, e1[1] * inv, e1[2] * inv, e1[3] * inv);
    *(float4*)(r2 + lane * 4) = make_float4(e2[0] * inv, e2[1] * inv, e2[2] * inv, e2[3] * inv);
}

// ---- per-line output GEMM O = A @ V, V via cp.async, A via LDG+STS transpose ----
// grid (512, 2 chalf, 2 br), block 256, hh-chunks of 16, double-buffered
__global__ __launch_bounds__(256) void kern_out()
{
    __shared__ __align__(16) float As[2][16][132];
    __shared__ __align__(16) float Vs[2][16][132];
    const int l = blockIdx.x, chf = blockIdx.y, br = blockIdx.z;
    const float* A = (br ? g_EW : g_EH) + (size_t)l * 16384;
    const float* V = (br ? g_vW : g_vH) + (size_t)l * 32768 + chf * 128;
    float* O = (br ? g_rO : g_cO) + (size_t)l * 32768 + chf * 128;
    const int t = threadIdx.x;
    const int tj = t & 15, ti = t >> 4;
    const int i0 = ti * 8, j0 = tj * 8;
    const unsigned vs_u = (unsigned)__cvta_generic_to_shared(&Vs[0][0][0]);

    // A-load indices (per round r: lin = t + 256r): k row, h4 group of 4
    const int ak = t >> 2;            // 0..63 (round adds 64)
    const int ah = (t & 3) << 2;      // 0,4,8,12

    ull acc2[8][4];
    #pragma unroll
    for (int u = 0; u < 8; u++)
        #pragma unroll
        for (int v = 0; v < 4; v++) acc2[u][v] = 0ULL;

    // prologue: chunk 0
    float4 a0 = *(const float4*)(A + (size_t)ak * 128 + ah);
    float4 a1 = *(const float4*)(A + (size_t)(ak + 64) * 128 + ah);
    {
        #pragma unroll
        for (int r = 0; r < 2; r++) {
            int lin = t + r * 256;
            int hh = lin >> 5, c4 = (lin & 31) << 2;
            cpa16(vs_u + (unsigned)((hh * 132 + c4) * 4), V + (size_t)hh * 256 + c4);
        }
        cpa_commit();
    }
    As[0][ah + 0][ak] = a0.x; As[0][ah + 1][ak] = a0.y;
    As[0][ah + 2][ak] = a0.z; As[0][ah + 3][ak] = a0.w;
    As[0][ah + 0][ak + 64] = a1.x; As[0][ah + 1][ak + 64] = a1.y;
    As[0][ah + 2][ak + 64] = a1.z; As[0][ah + 3][ak + 64] = a1.w;

    for (int hc = 0; hc < 8; hc++) {
        const int buf = hc & 1;
        cpa_wait<0>();
        __syncthreads();    // chunk hc visible everywhere; buf^1 free
        float4 n0, n1;
        if (hc < 7) {
            const int nb = buf ^ 1, hn = hc + 1;
            n0 = *(const float4*)(A + (size_t)ak * 128 + hn * 16 + ah);
            n1 = *(const float4*)(A + (size_t)(ak + 64) * 128 + hn * 16 + ah);
            #pragma unroll
            for (int r = 0; r < 2; r++) {
                int lin = t + r * 256;
                int hh = lin >> 5, c4 = (lin & 31) << 2;
                cpa16(vs_u + (unsigned)((nb * 2112 + hh * 132 + c4) * 4),
                      V + (size_t)(hn * 16 + hh) * 256 + c4);
            }
            cpa_commit();
        }
        #pragma unroll
        for (int hh = 0; hh < 16; hh++) {
            float4 aa = *(const float4*)&As[buf][hh][i0];
            float4 ab = *(const float4*)&As[buf][hh][i0 + 4];
            ull ad[8] = {dup2(aa.x), dup2(aa.y), dup2(aa.z), dup2(aa.w),
                         dup2(ab.x), dup2(ab.y), dup2(ab.z), dup2(ab.w)};
            const ull* vp = (const ull*)&Vs[buf][hh][j0];
            ull b0 = vp[0], b1 = vp[1], b2 = vp[2], b3 = vp[3];
            #pragma unroll
            for (int u = 0; u < 8; u++) {
                ffma2(acc2[u][0], ad[u], b0);
                ffma2(acc2[u][1], ad[u], b1);
                ffma2(acc2[u][2], ad[u], b2);
                ffma2(acc2[u][3], ad[u], b3);
            }
        }
        if (hc < 7) {
            const int nb = buf ^ 1;
            As[nb][ah + 0][ak] = n0.x; As[nb][ah + 1][ak] = n0.y;
            As[nb][ah + 2][ak] = n0.z; As[nb][ah + 3][ak] = n0.w;
            As[nb][ah + 0][ak + 64] = n1.x; As[nb][ah + 1][ak + 64] = n1.y;
            As[nb][ah + 2][ak + 64] = n1.z; As[nb][ah + 3][ak + 64] = n1.w;
        }
    }

    #pragma unroll
    for (int u = 0; u < 8; u++) {
        float2 p0 = u2f(acc2[u][0]), p1 = u2f(acc2[u][1]);
        float2 p2 = u2f(acc2[u][2]), p3 = u2f(acc2[u][3]);
        *(float4*)(O + (size_t)(i0 + u) * 256 + j0)     = make_float4(p0.x, p0.y, p1.x, p1.y);
        *(float4*)(O + (size_t)(i0 + u) * 256 + j0 + 4) = make_float4(p2.x, p2.y, p3.x, p3.y);
    }
}

// ---- combine: out = gamma*(colO + rowO) + x: grid (128 h, 8 ctile, 4 b), block 256 ----
__global__ void kern_combine(const float* __restrict__ x, const float* __restrict__ gamma,
                             float* __restrict__ out)
{
    __shared__ __align__(16) float s[32][132];
    const int h = blockIdx.x, ct = blockIdx.y, b = blockIdx.z;
    const int c0 = ct * 32, t = threadIdx.x;
    #pragma unroll
    for (int r = 0; r < 4; r++) {
        int lin = t + r * 256;
        int w = lin >> 3, c4 = (lin & 7) << 2;
        float4 a = *(const float4*)(g_cO + (((size_t)(b * 128 + w)) * 128 + h) * 256 + c0 + c4);
        float4 bb = *(const float4*)(g_rO + (((size_t)(b * 128 + h)) * 128 + w) * 256 + c0 + c4);
        s[c4][w] = a.x + bb.x; s[c4 + 1][w] = a.y + bb.y;
        s[c4 + 2][w] = a.z + bb.z; s[c4 + 3][w] = a.w + bb.w;
    }
    __syncthreads();
    float g = gamma[0];
    #pragma unroll
    for (int r = 0; r < 4; r++) {
        int lin = t + r * 256;
        int c = lin >> 5, w4 = (lin & 31) << 2;
        size_t oidx = (((size_t)b * 256 + c0 + c) * 128 + h) * 128 + w4;
        float4 xv = *(const float4*)(x + oidx);
        float4 o;
        o.x = g * s[c][w4] + xv.x;
        o.y = g * s[c][w4 + 1] + xv.y;
        o.z = g * s[c][w4 + 2] + xv.z;
        o.w = g * s[c][w4 + 3] + xv.w;
        *(float4*)(out + oidx) = o;
    }
}

extern "C" void kernel_launch(void* const* d_in, const int* in_sizes, int n_in,
                              void* d_out, int out_size)
{
    const float* x      = (const float*)d_in[0];
    const float* Wq     = (const float*)d_in[1];
    const float* bq     = (const float*)d_in[2];
    const float* Wk     = (const float*)d_in[3];
    const float* bk     = (const float*)d_in[4];
    const float* Wv     = (const float*)d_in[5];
    const float* bv     = (const float*)d_in[6];
    const float* gamma  = (const float*)d_in[7];
    const float* offs   = (const float*)d_in[8];
    float* out = (float*)d_out;

    kern_prep<<<1, 512>>>(offs, out, out_size - 1);
    kern_wt<<<320, 256>>>(Wq, bq, Wk, bk, Wv, bv);
    kern_proj<<<dim3(128, 5, 4), 256>>>(x);
    kern_sample<<<dim3(16384, 2), 320>>>();
    kern_energy<<<dim3(512, 2), 256>>>();
    kern_softmax<<<8192, 256>>>();
    kern_out<<<dim3(512, 2, 2), 256>>>();
    kern_combine<<<dim3(128, 8, 4), 256>>>(x, gamma, out);
}

// round 11
// speedup vs baseline: 1.8295x; 1.1880x over previous
#include <cuda_runtime.h>
#include <cstdint>
#include <math.h>

#define OFFD 131

__device__ float g_qH[512*128*32];
__device__ float g_kH[512*128*32];
__device__ float g_qW[512*128*32];
__device__ float g_kW[512*128*32];
__device__ float g_vH[512*128*256];
__device__ float g_vW[512*128*256];
__device__ float g_p0[128*128*320];
__device__ float g_EH[512*128*128];
__device__ float g_EW[512*128*128];
__device__ float g_cO[512*128*256];
__device__ float g_rO[512*128*256];
__device__ float g_dX[129][2];
__device__ float g_dY[129][2];
__device__ float g_Wt[256*320];
__device__ float g_bias[320];

typedef unsigned long long ull;

__device__ __forceinline__ void ffma2(ull& d, ull a, ull b) {
    asm("fma.rn.f32x2 %0, %1, %2, %0;" : "+l"(d) : "l"(a), "l"(b));
}
__device__ __forceinline__ ull dup2(float x) {
    ull r; asm("mov.b64 %0, {%1, %1};" : "=l"(r) : "f"(x)); return r;
}
__device__ __forceinline__ float2 u2f(ull v) {
    float2 f; asm("mov.b64 {%0, %1}, %2;" : "=f"(f.x), "=f"(f.y) : "l"(v)); return f;
}
__device__ __forceinline__ void cpa16(unsigned dst, const float* src) {
    asm volatile("cp.async.ca.shared.global [%0], [%1], 16;" :: "r"(dst), "l"(src));
}
__device__ __forceinline__ void cpa_commit() {
    asm volatile("cp.async.commit_group;");
}
template<int N> __device__ __forceinline__ void cpa_wait() {
    asm volatile("cp.async.wait_group %0;" :: "n"(N));
}
__device__ __forceinline__ void mma_tf32(float* d, const uint32_t* a, const uint32_t* b) {
    asm volatile("mma.sync.aligned.m16n8k8.row.col.f32.tf32.tf32.f32 "
                 "{%0,%1,%2,%3}, {%4,%5,%6,%7}, {%8,%9}, {%0,%1,%2,%3};"
                 : "+f"(d[0]), "+f"(d[1]), "+f"(d[2]), "+f"(d[3])
                 : "r"(a[0]), "r"(a[1]), "r"(a[2]), "r"(a[3]), "r"(b[0]), "r"(b[1]));
}

// ---- offset pooling + regloss ----
__global__ void kern_prep(const float* __restrict__ off, float* __restrict__ out, int regIdx)
{
    const int t = threadIdx.x;
    const float inv9 = 1.0f / 9.0f;
    for (int idx = t; idx < 258; idx += 512) {
        int r = idx % 129, ch = idx / 129;
        const float* o = off + ch * OFFD * OFFD;
        float s = 0.f;
        #pragma unroll
        for (int i = 0; i < 3; i++)
            #pragma unroll
            for (int j = 0; j < 3; j++) s += o[(r + i) * OFFD + 64 + j];
        g_dX[r][ch] = s * inv9;
    }
    for (int idx = t; idx < 258; idx += 512) {
        int c = idx % 129, ch = idx / 129;
        const float* o = off + ch * OFFD * OFFD;
        float s = 0.f;
        #pragma unroll
        for (int i = 0; i < 3; i++)
            #pragma unroll
            for (int j = 0; j < 3; j++) s += o[(64 + i) * OFFD + c + j];
        g_dY[c][ch] = s * inv9;
    }
    float s1 = 0.f, s2 = 0.f;
    for (int i = t; i < OFFD * OFFD; i += 512) {
        float d = off[i] - off[OFFD * OFFD + i];
        s1 += d * d;
    }
    for (int i = t; i < 2 * 130 * OFFD; i += 512) {
        int ch = i / (130 * OFFD);
        int rem = i - ch * 130 * OFFD;
        int r = rem / OFFD, c = rem - r * OFFD;
        float d = off[ch * OFFD * OFFD + r * OFFD + c] - off[ch * OFFD * OFFD + (r + 1) * OFFD + c];
        s2 += d * d;
    }
    __shared__ float sh1[512], sh2[512];
    sh1[t] = s1; sh2[t] = s2;
    __syncthreads();
    for (int s = 256; s > 0; s >>= 1) {
        if (t < s) { sh1[t] += sh1[t + s]; sh2[t] += sh2[t + s]; }
        __syncthreads();
    }
    if (t == 0)
        out[regIdx] = sh1[0] / (float)(OFFD * OFFD) + sh2[0] / (float)(2 * 130 * OFFD);
}

// ---- weight transpose ----
__global__ void kern_wt(const float* __restrict__ Wq, const float* __restrict__ bq,
                        const float* __restrict__ Wk, const float* __restrict__ bk,
                        const float* __restrict__ Wv, const float* __restrict__ bv)
{
    const int o = blockIdx.x;
    const int c = threadIdx.x;
    const float* row = (o < 32) ? (Wq + (size_t)o * 256)
                      : (o < 64) ? (Wk + (size_t)(o - 32) * 256)
                                 : (Wv + (size_t)(o - 64) * 256);
    g_Wt[(size_t)c * 320 + o] = row[c];
    if (c == 0)
        g_bias[o] = (o < 32) ? bq[o] : (o < 64) ? bk[o - 32] : bv[o - 64];
}

// ---- fused QKV projection GEMM (cp.async.ca double-buffered) ----
__global__ __launch_bounds__(256) void kern_proj(const float* __restrict__ x)
{
    __shared__ __align__(16) float Xs[2][32][128];
    __shared__ __align__(16) float Ws[2][32][64];
    float (*Ot)[68] = (float (*)[68])&Xs[0][0][0];

    const int h = blockIdx.x, ot = blockIdx.y, b = blockIdx.z;
    const int t = threadIdx.x;
    const int tw = t & 15, to = t >> 4;
    const int o0 = ot * 64;
    const float* xb = x + ((size_t)b * 256) * 16384 + (size_t)h * 128;

    const unsigned xs_u = (unsigned)__cvta_generic_to_shared(&Xs[0][0][0]);
    const unsigned ws_u = (unsigned)__cvta_generic_to_shared(&Ws[0][0][0]);

    ull acc2[4][4];
    #pragma unroll
    for (int j = 0; j < 4; j++)
        #pragma unroll
        for (int i = 0; i < 4; i++) acc2[j][i] = 0ULL;

    {
        #pragma unroll
        for (int r = 0; r < 4; r++) {
            int lin = t + r * 256;
            int row = lin >> 5, col = (lin & 31) << 2;
            cpa16(xs_u + (unsigned)((row * 128 + col) * 4), xb + (size_t)row * 16384 + col);
        }
        #pragma unroll
        for (int r = 0; r < 2; r++) {
            int lin = t + r * 256;
            int row = lin >> 4, o4 = (lin & 15) << 2;
            cpa16(ws_u + (unsigned)((row * 64 + o4) * 4), g_Wt + (size_t)row * 320 + o0 + o4);
        }
        cpa_commit();
    }

    for (int kc = 0; kc < 8; kc++) {
        const int buf = kc & 1;
        cpa_wait<0>();
        __syncthreads();
        if (kc < 7) {
            const int nb = buf ^ 1, kn = kc + 1;
            #pragma unroll
            for (int r = 0; r < 4; r++) {
                int lin = t + r * 256;
                int row = lin >> 5, col = (lin & 31) << 2;
                cpa16(xs_u + (unsigned)((nb * 4096 + row * 128 + col) * 4),
                      xb + (size_t)(kn * 32 + row) * 16384 + col);
            }
            #pragma unroll
            for (int r = 0; r < 2; r++) {
                int lin = t + r * 256;
                int row = lin >> 4, o4 = (lin & 15) << 2;
                cpa16(ws_u + (unsigned)((nb * 2048 + row * 64 + o4) * 4),
                      g_Wt + (size_t)(kn * 32 + row) * 320 + o0 + o4);
            }
            cpa_commit();
        }
        const float* Xb = &Xs[buf][0][0];
        const float* Wb = &Ws[buf][0][0];
        #pragma unroll
        for (int cc = 0; cc < 32; cc++) {
            const ull* xp = (const ull*)(Xb + cc * 128 + tw * 8);
            ull x0 = xp[0], x1 = xp[1], x2 = xp[2], x3 = xp[3];
            float4 wv = *(const float4*)(Wb + cc * 64 + to * 4);
            ull wd[4] = {dup2(wv.x), dup2(wv.y), dup2(wv.z), dup2(wv.w)};
            #pragma unroll
            for (int j = 0; j < 4; j++) {
                ffma2(acc2[j][0], wd[j], x0);
                ffma2(acc2[j][1], wd[j], x1);
                ffma2(acc2[j][2], wd[j], x2);
                ffma2(acc2[j][3], wd[j], x3);
            }
        }
    }
    __syncthreads();

    #pragma unroll
    for (int j = 0; j < 4; j++) {
        float bs = g_bias[o0 + to * 4 + j];
        #pragma unroll
        for (int i2 = 0; i2 < 4; i2++) {
            float2 f = u2f(acc2[j][i2]);
            Ot[tw * 8 + 2 * i2][to * 4 + j]     = f.x + bs;
            Ot[tw * 8 + 2 * i2 + 1][to * 4 + j] = f.y + bs;
        }
    }
    __syncthreads();

    if (ot == 0) {
        int w = t >> 1, half = t & 1;
        const float* src = &Ot[w][half * 32];
        if (b > 0) {
            float* dst = half ? (g_kH + (((size_t)(b * 128 + w)) * 128 + h) * 32)
                              : (g_qH + (((size_t)(b * 128 + w)) * 128 + h) * 32);
            #pragma unroll
            for (int i = 0; i < 8; i++) ((float4*)dst)[i] = ((const float4*)src)[i];
            float* dq = g_qW + ((size_t)(b * 128 + h)) * 4096;
            float* dk = g_kW + ((size_t)(b * 128 + h)) * 4096;
            #pragma unroll
            for (int r = 0; r < 4; r++) {
                int e = (t + r * 256) << 2;
                int wI = e >> 5, cI = e & 31;
                *(float4*)(dq + e) = *(const float4*)&Ot[wI][cI];
                *(float4*)(dk + e) = *(const float4*)&Ot[wI][32 + cI];
            }
        } else {
            float* dst = g_p0 + ((size_t)(h * 128 + w)) * 320 + half * 32;
            #pragma unroll
            for (int i = 0; i < 8; i++) ((float4*)dst)[i] = ((const float4*)src)[i];
        }
    } else {
        const int c0v = (ot - 1) * 64;
        int w = t >> 1, half = t & 1;
        const float* src = &Ot[w][half * 32];
        if (b > 0) {
            float* dst = g_vH + (((size_t)(b * 128 + w)) * 128 + h) * 256 + c0v + half * 32;
            #pragma unroll
            for (int i = 0; i < 8; i++) ((float4*)dst)[i] = ((const float4*)src)[i];
            float* dw = g_vW + ((size_t)(b * 128 + h)) * 32768 + c0v;
            #pragma unroll
            for (int r = 0; r < 8; r++) {
                int e = (t + r * 256) << 2;
                int wI = e >> 6, cI = e & 63;
                *(float4*)(dw + (size_t)wI * 256 + cI) = *(const float4*)&Ot[wI][cI];
            }
        } else {
            float* dst = g_p0 + ((size_t)(h * 128 + w)) * 320 + 64 + c0v + half * 32;
            #pragma unroll
            for (int i = 0; i < 8; i++) ((float4*)dst)[i] = ((const float4*)src)[i];
        }
    }
}

// ---- deformable bilinear sampling: grid (16384, 2), block 320 ----
__global__ void kern_sample()
{
    const int pt = blockIdx.x, br = blockIdx.y;
    const int k = pt >> 7, pos = pt & 127;
    float px, py;
    if (br == 0) {
        int r = pos + 1;
        px = (-1.0f + k * 0.015625f) + g_dX[r][0];
        py = (-1.0f + r * 0.015625f) + g_dX[r][1];
    } else {
        int ci = pos + 1;
        px = (-1.0f + ci * 0.015625f) + g_dY[ci][0];
        py = (-1.0f + k * 0.015625f) + g_dY[ci][1];
    }
    float fx = (px + 1.0f) * 0.5f * 127.0f;
    float fy = (py + 1.0f) * 0.5f * 127.0f;
    float x0f = floorf(fx), y0f = floorf(fy);
    float wx = fx - x0f, wy = fy - y0f;
    int x0 = (int)x0f, y0 = (int)y0f;
    bool vx0 = (x0 >= 0) && (x0 < 128);
    bool vx1 = (x0 + 1 >= 0) && (x0 + 1 < 128);
    bool vy0 = (y0 >= 0) && (y0 < 128);
    bool vy1 = (y0 + 1 >= 0) && (y0 + 1 < 128);

    const int c = threadIdx.x;
    float acc = 0.f;
    if (vx0 && vy0) acc += g_p0[((size_t)(y0 * 128 + x0)) * 320 + c] * ((1.f - wx) * (1.f - wy));
    if (vx1 && vy0) acc += g_p0[((size_t)(y0 * 128 + x0 + 1)) * 320 + c] * (wx * (1.f - wy));
    if (vx0 && vy1) acc += g_p0[((size_t)((y0 + 1) * 128 + x0)) * 320 + c] * ((1.f - wx) * wy);
    if (vx1 && vy1) acc += g_p0[((size_t)((y0 + 1) * 128 + x0 + 1)) * 320 + c] * (wx * wy);

    size_t lp = (size_t)k * 128 + pos;
    if (br == 0) {
        if (c < 32)      g_qH[lp * 32 + c] = acc;
        else if (c < 64) g_kH[lp * 32 + (c - 32)] = acc;
        else             g_vH[lp * 256 + (c - 64)] = acc;
    } else {
        if (c < 32)      g_qW[lp * 32 + c] = acc;
        else if (c < 64) g_kW[lp * 32 + (c - 32)] = acc;
        else             g_vW[lp * 256 + (c - 64)] = acc;
    }
}

// ---- per-line energy GEMM E = Q @ K^T: grid (512, 2), block 256 ----
__global__ __launch_bounds__(256) void kern_energy()
{
    __shared__ __align__(16) float Qt[32][132];
    __shared__ __align__(16) float Kt[32][132];
    const int l = blockIdx.x, br = blockIdx.y;
    const float* Q = (br ? g_qW : g_qH) + (size_t)l * 4096;
    const float* K = (br ? g_kW : g_kH) + (size_t)l * 4096;
    float* E = (br ? g_EW : g_EH) + (size_t)l * 16384;
    const int t = threadIdx.x;

    #pragma unroll
    for (int r = 0; r < 4; r++) {
        int lin = t + r * 256;
        int p = lin >> 3, c4 = (lin & 7) << 2;
        float4 q = *(const float4*)(Q + (size_t)p * 32 + c4);
        Qt[c4][p] = q.x; Qt[c4 + 1][p] = q.y; Qt[c4 + 2][p] = q.z; Qt[c4 + 3][p] = q.w;
        float4 kk = *(const float4*)(K + (size_t)p * 32 + c4);
        Kt[c4][p] = kk.x; Kt[c4 + 1][p] = kk.y; Kt[c4 + 2][p] = kk.z; Kt[c4 + 3][p] = kk.w;
    }
    __syncthreads();

    const int tj = t & 15, ti = t >> 4;
    const int i0 = ti * 8, j0 = tj * 8;
    ull acc2[8][4];
    #pragma unroll
    for (int u = 0; u < 8; u++)
        #pragma unroll
        for (int v = 0; v < 4; v++) acc2[u][v] = 0ULL;

    #pragma unroll
    for (int c = 0; c < 32; c++) {
        float4 qa = *(const float4*)&Qt[c][i0];
        float4 qb = *(const float4*)&Qt[c][i0 + 4];
        ull ad[8] = {dup2(qa.x), dup2(qa.y), dup2(qa.z), dup2(qa.w),
                     dup2(qb.x), dup2(qb.y), dup2(qb.z), dup2(qb.w)};
        const ull* kp = (const ull*)&Kt[c][j0];
        ull b0 = kp[0], b1 = kp[1], b2 = kp[2], b3 = kp[3];
        #pragma unroll
        for (int u = 0; u < 8; u++) {
            ffma2(acc2[u][0], ad[u], b0);
            ffma2(acc2[u][1], ad[u], b1);
            ffma2(acc2[u][2], ad[u], b2);
            ffma2(acc2[u][3], ad[u], b3);
        }
    }
    #pragma unroll
    for (int u = 0; u < 8; u++) {
        float2 p0 = u2f(acc2[u][0]), p1 = u2f(acc2[u][1]);
        float2 p2 = u2f(acc2[u][2]), p3 = u2f(acc2[u][3]);
        *(float4*)(E + (size_t)(i0 + u) * 128 + j0)     = make_float4(p0.x, p0.y, p1.x, p1.y);
        *(float4*)(E + (size_t)(i0 + u) * 128 + j0 + 4) = make_float4(p2.x, p2.y, p3.x, p3.y);
    }
}

// ---- joint softmax ----
__global__ void kern_softmax()
{
    int gw = (blockIdx.x * blockDim.x + threadIdx.x) >> 5;
    int lane = threadIdx.x & 31;
    if (gw >= 65536) return;
    int b = gw >> 14;
    int rem = gw & 16383;
    int h = rem >> 7, w = rem & 127;
    float* r1 = g_EH + (((size_t)(b * 128 + w)) * 128 + h) * 128;
    float* r2 = g_EW + (((size_t)(b * 128 + h)) * 128 + w) * 128;
    float4 a = *(float4*)(r1 + lane * 4);
    float4 c = *(float4*)(r2 + lane * 4);
    float e1[4] = {a.x, a.y, a.z, a.w};
    float e2[4] = {c.x, c.y, c.z, c.w};
    float m = -INFINITY;
    #pragma unroll
    for (int u = 0; u < 4; u++) {
        if (lane * 4 + u != h) m = fmaxf(m, e1[u]);
        m = fmaxf(m, e2[u]);
    }
    #pragma unroll
    for (int s = 16; s > 0; s >>= 1) m = fmaxf(m, __shfl_xor_sync(0xffffffffu, m, s));
    float sum = 0.f;
    #pragma unroll
    for (int u = 0; u < 4; u++) {
        e1[u] = (lane * 4 + u == h) ? 0.f : __expf(e1[u] - m);
        sum += e1[u];
        e2[u] = __expf(e2[u] - m);
        sum += e2[u];
    }
    #pragma unroll
    for (int s = 16; s > 0; s >>= 1) sum += __shfl_xor_sync(0xffffffffu, sum, s);
    float inv = 1.0f / sum;
    *(float4*)(r1 + lane * 4) = make_float4(e1[0] * inv, e1[1] * inv, e1[2] * inv, e1[3] * inv);
    *(float4*)(r2 + lane * 4) = make_float4(e2[0] * inv, e2[1] * inv, e2[2] * inv, e2[3] * inv);
}

// ---- per-line output GEMM via mma.sync tf32 ----
// grid (512 lines, 2 chalf, 2 br), block 256 (8 warps, 4x2 warp grid, warp tile 32x64)
// dynamic smem: As[2][128][36] + Vs[2][32][132] = 70656 B
#define OSM_TOTAL 70656

__global__ __launch_bounds__(256) void kern_out_mma()
{
    extern __shared__ __align__(16) float osm[];
    float* As = osm;             // [2][128][36]
    float* Vs = osm + 9216;      // [2][32][132]
    const int l = blockIdx.x, chf = blockIdx.y, br = blockIdx.z;
    const float* A = (br ? g_EW : g_EH) + (size_t)l * 16384;
    const float* V = (br ? g_vW : g_vH) + (size_t)l * 32768 + chf * 128;
    float* O = (br ? g_rO : g_cO) + (size_t)l * 32768 + chf * 128;
    const int t = threadIdx.x;
    const int w = t >> 5, lane = t & 31;
    const int g = lane >> 2, tig = lane & 3;
    const int kbase = (w >> 1) * 32, cbase = (w & 1) * 64;
    const unsigned as_u = (unsigned)__cvta_generic_to_shared(As);
    const unsigned vs_u = (unsigned)__cvta_generic_to_shared(Vs);

    float acc[2][8][4];
    #pragma unroll
    for (int mt = 0; mt < 2; mt++)
        #pragma unroll
        for (int nt = 0; nt < 8; nt++)
            #pragma unroll
            for (int i = 0; i < 4; i++) acc[mt][nt][i] = 0.f;

    // prologue: h-chunk 0
    {
        #pragma unroll
        for (int r = 0; r < 4; r++) {
            int idx = t + r * 256;
            int k = idx >> 3, seg = idx & 7;
            cpa16(as_u + (unsigned)((k * 36 + seg * 4) * 4), A + (size_t)k * 128 + seg * 4);
        }
        #pragma unroll
        for (int r = 0; r < 4; r++) {
            int idx = t + r * 256;
            int hh = idx >> 5, seg = idx & 31;
            cpa16(vs_u + (unsigned)((hh * 132 + seg * 4) * 4), V + (size_t)hh * 256 + seg * 4);
        }
        cpa_commit();
    }

    for (int hc = 0; hc < 4; hc++) {
        const int buf = hc & 1;
        cpa_wait<0>();
        __syncthreads();
        if (hc < 3) {
            const int nb = buf ^ 1, hn = (hc + 1) * 32;
            #pragma unroll
            for (int r = 0; r < 4; r++) {
                int idx = t + r * 256;
                int k = idx >> 3, seg = idx & 7;
                cpa16(as_u + (unsigned)((nb * 4608 + k * 36 + seg * 4) * 4),
                      A + (size_t)k * 128 + hn + seg * 4);
            }
            #pragma unroll
            for (int r = 0; r < 4; r++) {
                int idx = t + r * 256;
                int hh = idx >> 5, seg = idx & 31;
                cpa16(vs_u + (unsigned)((nb * 4224 + hh * 132 + seg * 4) * 4),
                      V + (size_t)(hn + hh) * 256 + seg * 4);
            }
            cpa_commit();
        }
        const float* Ab = As + buf * 4608;
        const float* Vb = Vs + buf * 4224;
        #pragma unroll
        for (int hs = 0; hs < 4; hs++) {
            const int hb = hs * 8;
            uint32_t af[2][4];
            #pragma unroll
            for (int mt = 0; mt < 2; mt++) {
                const float* ar = Ab + (kbase + mt * 16 + g) * 36 + hb + tig;
                af[mt][0] = __float_as_uint(ar[0]);
                af[mt][1] = __float_as_uint(ar[8 * 36]);
                af[mt][2] = __float_as_uint(ar[4]);
                af[mt][3] = __float_as_uint(ar[8 * 36 + 4]);
            }
            #pragma unroll
            for (int nt = 0; nt < 8; nt++) {
                const float* vr = Vb + (hb + tig) * 132 + cbase + nt * 8 + g;
                uint32_t bf[2];
                bf[0] = __float_as_uint(vr[0]);
                bf[1] = __float_as_uint(vr[4 * 132]);
                mma_tf32(acc[0][nt], af[0], bf);
                mma_tf32(acc[1][nt], af[1], bf);
            }
        }
    }

    #pragma unroll
    for (int mt = 0; mt < 2; mt++)
        #pragma unroll
        for (int nt = 0; nt < 8; nt++) {
            int row = kbase + mt * 16 + g;
            int col = cbase + nt * 8 + 2 * tig;
            *(float2*)(O + (size_t)row * 256 + col)       = make_float2(acc[mt][nt][0], acc[mt][nt][1]);
            *(float2*)(O + (size_t)(row + 8) * 256 + col) = make_float2(acc[mt][nt][2], acc[mt][nt][3]);
        }
}

// ---- combine ----
__global__ void kern_combine(const float* __restrict__ x, const float* __restrict__ gamma,
                             float* __restrict__ out)
{
    __shared__ __align__(16) float s[32][132];
    const int h = blockIdx.x, ct = blockIdx.y, b = blockIdx.z;
    const int c0 = ct * 32, t = threadIdx.x;
    #pragma unroll
    for (int r = 0; r < 4; r++) {
        int lin = t + r * 256;
        int w = lin >> 3, c4 = (lin & 7) << 2;
        float4 a = *(const float4*)(g_cO + (((size_t)(b * 128 + w)) * 128 + h) * 256 + c0 + c4);
        float4 bb = *(const float4*)(g_rO + (((size_t)(b * 128 + h)) * 128 + w) * 256 + c0 + c4);
        s[c4][w] = a.x + bb.x; s[c4 + 1][w] = a.y + bb.y;
        s[c4 + 2][w] = a.z + bb.z; s[c4 + 3][w] = a.w + bb.w;
    }
    __syncthreads();
    float g = gamma[0];
    #pragma unroll
    for (int r = 0; r < 4; r++) {
        int lin = t + r * 256;
        int c = lin >> 5, w4 = (lin & 31) << 2;
        size_t oidx = (((size_t)b * 256 + c0 + c) * 128 + h) * 128 + w4;
        float4 xv = *(const float4*)(x + oidx);
        float4 o;
        o.x = g * s[c][w4] + xv.x;
        o.y = g * s[c][w4 + 1] + xv.y;
        o.z = g * s[c][w4 + 2] + xv.z;
        o.w = g * s[c][w4 + 3] + xv.w;
        *(float4*)(out + oidx) = o;
    }
}

extern "C" void kernel_launch(void* const* d_in, const int* in_sizes, int n_in,
                              void* d_out, int out_size)
{
    const float* x      = (const float*)d_in[0];
    const float* Wq     = (const float*)d_in[1];
    const float* bq     = (const float*)d_in[2];
    const float* Wk     = (const float*)d_in[3];
    const float* bk     = (const float*)d_in[4];
    const float* Wv     = (const float*)d_in[5];
    const float* bv     = (const float*)d_in[6];
    const float* gamma  = (const float*)d_in[7];
    const float* offs   = (const float*)d_in[8];
    float* out = (float*)d_out;

    cudaFuncSetAttribute(kern_out_mma, cudaFuncAttributeMaxDynamicSharedMemorySize, OSM_TOTAL);

    kern_prep<<<1, 512>>>(offs, out, out_size - 1);
    kern_wt<<<320, 256>>>(Wq, bq, Wk, bk, Wv, bv);
    kern_proj<<<dim3(128, 5, 4), 256>>>(x);
    kern_sample<<<dim3(16384, 2), 320>>>();
    kern_energy<<<dim3(512, 2), 256>>>();
    kern_softmax<<<8192, 256>>>();
    kern_out_mma<<<dim3(512, 2, 2), 256, OSM_TOTAL>>>();
    kern_combine<<<dim3(128, 8, 4), 256>>>(x, gamma, out);
}

// round 12
// speedup vs baseline: 2.4559x; 1.3424x over previous
#include <cuda_runtime.h>
#include <cstdint>
#include <math.h>

#define OFFD 131

__device__ float g_qH[512*128*32];
__device__ float g_kH[512*128*32];
__device__ float g_qW[512*128*32];
__device__ float g_kW[512*128*32];
__device__ float g_vH[512*128*256];
__device__ float g_vW[512*128*256];
__device__ float g_p0[128*128*320];
__device__ float g_EH[512*128*128];
__device__ float g_EW[512*128*128];
__device__ float g_cO[512*128*256];
__device__ float g_rO[512*128*256];
__device__ float g_dX[129][2];
__device__ float g_dY[129][2];
__device__ float g_Wt[256*320];
__device__ float g_bias[320];
__device__ float g_xT[4*128*128*256];   // [b][h][w][c]

typedef unsigned long long ull;

__device__ __forceinline__ void ffma2(ull& d, ull a, ull b) {
    asm("fma.rn.f32x2 %0, %1, %2, %0;" : "+l"(d) : "l"(a), "l"(b));
}
__device__ __forceinline__ ull dup2(float x) {
    ull r; asm("mov.b64 %0, {%1, %1};" : "=l"(r) : "f"(x)); return r;
}
__device__ __forceinline__ float2 u2f(ull v) {
    float2 f; asm("mov.b64 {%0, %1}, %2;" : "=f"(f.x), "=f"(f.y) : "l"(v)); return f;
}
__device__ __forceinline__ void cpa16(unsigned dst, const float* src) {
    asm volatile("cp.async.ca.shared.global [%0], [%1], 16;" :: "r"(dst), "l"(src));
}
__device__ __forceinline__ void cpa_commit() {
    asm volatile("cp.async.commit_group;");
}
template<int N> __device__ __forceinline__ void cpa_wait() {
    asm volatile("cp.async.wait_group %0;" :: "n"(N));
}
__device__ __forceinline__ void mma_tf32(float* d, const uint32_t* a, const uint32_t* b) {
    asm volatile("mma.sync.aligned.m16n8k8.row.col.f32.tf32.tf32.f32 "
                 "{%0,%1,%2,%3}, {%4,%5,%6,%7}, {%8,%9}, {%0,%1,%2,%3};"
                 : "+f"(d[0]), "+f"(d[1]), "+f"(d[2]), "+f"(d[3])
                 : "r"(a[0]), "r"(a[1]), "r"(a[2]), "r"(a[3]), "r"(b[0]), "r"(b[1]));
}

// ---- offset pooling + regloss ----
__global__ void kern_prep(const float* __restrict__ off, float* __restrict__ out, int regIdx)
{
    const int t = threadIdx.x;
    const float inv9 = 1.0f / 9.0f;
    for (int idx = t; idx < 258; idx += 512) {
        int r = idx % 129, ch = idx / 129;
        const float* o = off + ch * OFFD * OFFD;
        float s = 0.f;
        #pragma unroll
        for (int i = 0; i < 3; i++)
            #pragma unroll
            for (int j = 0; j < 3; j++) s += o[(r + i) * OFFD + 64 + j];
        g_dX[r][ch] = s * inv9;
    }
    for (int idx = t; idx < 258; idx += 512) {
        int c = idx % 129, ch = idx / 129;
        const float* o = off + ch * OFFD * OFFD;
        float s = 0.f;
        #pragma unroll
        for (int i = 0; i < 3; i++)
            #pragma unroll
            for (int j = 0; j < 3; j++) s += o[(64 + i) * OFFD + c + j];
        g_dY[c][ch] = s * inv9;
    }
    float s1 = 0.f, s2 = 0.f;
    for (int i = t; i < OFFD * OFFD; i += 512) {
        float d = off[i] - off[OFFD * OFFD + i];
        s1 += d * d;
    }
    for (int i = t; i < 2 * 130 * OFFD; i += 512) {
        int ch = i / (130 * OFFD);
        int rem = i - ch * 130 * OFFD;
        int r = rem / OFFD, c = rem - r * OFFD;
        float d = off[ch * OFFD * OFFD + r * OFFD + c] - off[ch * OFFD * OFFD + (r + 1) * OFFD + c];
        s2 += d * d;
    }
    __shared__ float sh1[512], sh2[512];
    sh1[t] = s1; sh2[t] = s2;
    __syncthreads();
    for (int s = 256; s > 0; s >>= 1) {
        if (t < s) { sh1[t] += sh1[t + s]; sh2[t] += sh2[t + s]; }
        __syncthreads();
    }
    if (t == 0)
        out[regIdx] = sh1[0] / (float)(OFFD * OFFD) + sh2[0] / (float)(2 * 130 * OFFD);
}

// ---- weight transpose ----
__global__ void kern_wt(const float* __restrict__ Wq, const float* __restrict__ bq,
                        const float* __restrict__ Wk, const float* __restrict__ bk,
                        const float* __restrict__ Wv, const float* __restrict__ bv)
{
    const int o = blockIdx.x;
    const int c = threadIdx.x;
    const float* row = (o < 32) ? (Wq + (size_t)o * 256)
                      : (o < 64) ? (Wk + (size_t)(o - 32) * 256)
                                 : (Wv + (size_t)(o - 64) * 256);
    g_Wt[(size_t)c * 320 + o] = row[c];
    if (c == 0)
        g_bias[o] = (o < 32) ? bq[o] : (o < 64) ? bk[o - 32] : bv[o - 64];
}

// ---- x transpose: g_xT[b][h][w][c] = x[b][c][h][w]; grid (4 wt, 128 h, 4 b) ----
__global__ __launch_bounds__(256) void kern_xT(const float* __restrict__ x)
{
    __shared__ float sm[32][33];
    const int wt = blockIdx.x, h = blockIdx.y, b = blockIdx.z;
    const int t = threadIdx.x;
    const int lane = t & 31, row8 = t >> 5;
    const int w0 = wt * 32;
    for (int cc = 0; cc < 8; cc++) {
        #pragma unroll
        for (int r = 0; r < 4; r++) {
            int c = cc * 32 + row8 + r * 8;
            sm[row8 + r * 8][lane] = x[(((size_t)b * 256 + c) * 128 + h) * 128 + w0 + lane];
        }
        __syncthreads();
        #pragma unroll
        for (int r = 0; r < 4; r++) {
            int w = row8 + r * 8;
            g_xT[(((size_t)b * 128 + h) * 128 + w0 + w) * 256 + cc * 32 + lane] = sm[lane][w];
        }
        __syncthreads();
    }
}

// ---- Q/K projection (FFMA2, bit-exact): grid (h=128, 1, b=4), block 256 ----
__global__ __launch_bounds__(256) void kern_projqk(const float* __restrict__ x)
{
    __shared__ __align__(16) float Xs[2][32][128];
    __shared__ __align__(16) float Ws[2][32][64];
    float (*Ot)[68] = (float (*)[68])&Xs[0][0][0];

    const int h = blockIdx.x, b = blockIdx.z;
    const int t = threadIdx.x;
    const int tw = t & 15, to = t >> 4;
    const float* xb = x + ((size_t)b * 256) * 16384 + (size_t)h * 128;

    const unsigned xs_u = (unsigned)__cvta_generic_to_shared(&Xs[0][0][0]);
    const unsigned ws_u = (unsigned)__cvta_generic_to_shared(&Ws[0][0][0]);

    ull acc2[4][4];
    #pragma unroll
    for (int j = 0; j < 4; j++)
        #pragma unroll
        for (int i = 0; i < 4; i++) acc2[j][i] = 0ULL;

    {
        #pragma unroll
        for (int r = 0; r < 4; r++) {
            int lin = t + r * 256;
            int row = lin >> 5, col = (lin & 31) << 2;
            cpa16(xs_u + (unsigned)((row * 128 + col) * 4), xb + (size_t)row * 16384 + col);
        }
        #pragma unroll
        for (int r = 0; r < 2; r++) {
            int lin = t + r * 256;
            int row = lin >> 4, o4 = (lin & 15) << 2;
            cpa16(ws_u + (unsigned)((row * 64 + o4) * 4), g_Wt + (size_t)row * 320 + o4);
        }
        cpa_commit();
    }

    for (int kc = 0; kc < 8; kc++) {
        const int buf = kc & 1;
        cpa_wait<0>();
        __syncthreads();
        if (kc < 7) {
            const int nb = buf ^ 1, kn = kc + 1;
            #pragma unroll
            for (int r = 0; r < 4; r++) {
                int lin = t + r * 256;
                int row = lin >> 5, col = (lin & 31) << 2;
                cpa16(xs_u + (unsigned)((nb * 4096 + row * 128 + col) * 4),
                      xb + (size_t)(kn * 32 + row) * 16384 + col);
            }
            #pragma unroll
            for (int r = 0; r < 2; r++) {
                int lin = t + r * 256;
                int row = lin >> 4, o4 = (lin & 15) << 2;
                cpa16(ws_u + (unsigned)((nb * 2048 + row * 64 + o4) * 4),
                      g_Wt + (size_t)(kn * 32 + row) * 320 + o4);
            }
            cpa_commit();
        }
        const float* Xb = &Xs[buf][0][0];
        const float* Wb = &Ws[buf][0][0];
        #pragma unroll
        for (int cc = 0; cc < 32; cc++) {
            const ull* xp = (const ull*)(Xb + cc * 128 + tw * 8);
            ull x0 = xp[0], x1 = xp[1], x2 = xp[2], x3 = xp[3];
            float4 wv = *(const float4*)(Wb + cc * 64 + to * 4);
            ull wd[4] = {dup2(wv.x), dup2(wv.y), dup2(wv.z), dup2(wv.w)};
            #pragma unroll
            for (int j = 0; j < 4; j++) {
                ffma2(acc2[j][0], wd[j], x0);
                ffma2(acc2[j][1], wd[j], x1);
                ffma2(acc2[j][2], wd[j], x2);
                ffma2(acc2[j][3], wd[j], x3);
            }
        }
    }
    __syncthreads();

    #pragma unroll
    for (int j = 0; j < 4; j++) {
        float bs = g_bias[to * 4 + j];
        #pragma unroll
        for (int i2 = 0; i2 < 4; i2++) {
            float2 f = u2f(acc2[j][i2]);
            Ot[tw * 8 + 2 * i2][to * 4 + j]     = f.x + bs;
            Ot[tw * 8 + 2 * i2 + 1][to * 4 + j] = f.y + bs;
        }
    }
    __syncthreads();

    {
        int w = t >> 1, half = t & 1;
        const float* src = &Ot[w][half * 32];
        if (b > 0) {
            float* dst = half ? (g_kH + (((size_t)(b * 128 + w)) * 128 + h) * 32)
                              : (g_qH + (((size_t)(b * 128 + w)) * 128 + h) * 32);
            #pragma unroll
            for (int i = 0; i < 8; i++) ((float4*)dst)[i] = ((const float4*)src)[i];
            float* dq = g_qW + ((size_t)(b * 128 + h)) * 4096;
            float* dk = g_kW + ((size_t)(b * 128 + h)) * 4096;
            #pragma unroll
            for (int r = 0; r < 4; r++) {
                int e = (t + r * 256) << 2;
                int wI = e >> 5, cI = e & 31;
                *(float4*)(dq + e) = *(const float4*)&Ot[wI][cI];
                *(float4*)(dk + e) = *(const float4*)&Ot[wI][32 + cI];
            }
        } else {
            float* dst = g_p0 + ((size_t)(h * 128 + w)) * 320 + half * 32;
            #pragma unroll
            for (int i = 0; i < 8; i++) ((float4*)dst)[i] = ((const float4*)src)[i];
        }
    }
}

// ---- V projection via mma.sync tf32: grid (h=128, ot=4, b=4), block 256 ----
// O[128 w x 64 o] = xT[128 w x 256 c] . Wt[c][oc..oc+64]
#define PSM_TOTAL 54272

__global__ __launch_bounds__(256) void kern_projv()
{
    extern __shared__ __align__(16) float psm[];
    float* As = psm;             // [2][128][36]
    float* Ws = psm + 9216;      // [2][32][68]
    float (*Ot)[68] = (float (*)[68])psm;   // alias (used after compute)

    const int h = blockIdx.x, ot = blockIdx.y, b = blockIdx.z;
    const int t = threadIdx.x;
    const int w = t >> 5, lane = t & 31;
    const int g = lane >> 2, tig = lane & 3;
    const int mbase = (w >> 1) * 32, nbase = (w & 1) * 32;
    const int oc = 64 + ot * 64;
    const float* Xr = g_xT + (((size_t)b * 128 + h) * 128) * 256;
    const unsigned as_u = (unsigned)__cvta_generic_to_shared(As);
    const unsigned ws_u = (unsigned)__cvta_generic_to_shared(Ws);

    float acc[2][4][4];
    #pragma unroll
    for (int mt = 0; mt < 2; mt++)
        #pragma unroll
        for (int nt = 0; nt < 4; nt++)
            #pragma unroll
            for (int i = 0; i < 4; i++) acc[mt][nt][i] = 0.f;

    {
        #pragma unroll
        for (int r = 0; r < 4; r++) {
            int idx = t + r * 256;
            int m = idx >> 3, seg = idx & 7;
            cpa16(as_u + (unsigned)((m * 36 + seg * 4) * 4), Xr + (size_t)m * 256 + seg * 4);
        }
        #pragma unroll
        for (int r = 0; r < 2; r++) {
            int idx = t + r * 256;
            int k = idx >> 4, o4 = (idx & 15) << 2;
            cpa16(ws_u + (unsigned)((k * 68 + o4) * 4), g_Wt + (size_t)k * 320 + oc + o4);
        }
        cpa_commit();
    }

    for (int kc = 0; kc < 8; kc++) {
        const int buf = kc & 1;
        cpa_wait<0>();
        __syncthreads();
        if (kc < 7) {
            const int nb = buf ^ 1, kn = (kc + 1) * 32;
            #pragma unroll
            for (int r = 0; r < 4; r++) {
                int idx = t + r * 256;
                int m = idx >> 3, seg = idx & 7;
                cpa16(as_u + (unsigned)((nb * 4608 + m * 36 + seg * 4) * 4),
                      Xr + (size_t)m * 256 + kn + seg * 4);
            }
            #pragma unroll
            for (int r = 0; r < 2; r++) {
                int idx = t + r * 256;
                int k = idx >> 4, o4 = (idx & 15) << 2;
                cpa16(ws_u + (unsigned)((nb * 2176 + k * 68 + o4) * 4),
                      g_Wt + (size_t)(kn + k) * 320 + oc + o4);
            }
            cpa_commit();
        }
        const float* Ab = As + buf * 4608;
        const float* Wb = Ws + buf * 2176;
        #pragma unroll
        for (int hs = 0; hs < 4; hs++) {
            const int kb = hs * 8;
            uint32_t af[2][4];
            #pragma unroll
            for (int mt = 0; mt < 2; mt++) {
                const float* ar = Ab + (mbase + mt * 16 + g) * 36 + kb + tig;
                af[mt][0] = __float_as_uint(ar[0]);
                af[mt][1] = __float_as_uint(ar[8 * 36]);
                af[mt][2] = __float_as_uint(ar[4]);
                af[mt][3] = __float_as_uint(ar[8 * 36 + 4]);
            }
            #pragma unroll
            for (int nt = 0; nt < 4; nt++) {
                const float* br = Wb + (kb + tig) * 68 + nbase + nt * 8 + g;
                uint32_t bf[2];
                bf[0] = __float_as_uint(br[0]);
                bf[1] = __float_as_uint(br[4 * 68]);
                mma_tf32(acc[0][nt], af[0], bf);
                mma_tf32(acc[1][nt], af[1], bf);
            }
        }
    }
    __syncthreads();   // done reading As/Ws before aliasing Ot

    #pragma unroll
    for (int mt = 0; mt < 2; mt++)
        #pragma unroll
        for (int nt = 0; nt < 4; nt++) {
            int row = mbase + mt * 16 + g;
            int col = nbase + nt * 8 + 2 * tig;
            float b0 = g_bias[oc + col], b1 = g_bias[oc + col + 1];
            Ot[row][col]     = acc[mt][nt][0] + b0;
            Ot[row][col + 1] = acc[mt][nt][1] + b1;
            Ot[row + 8][col]     = acc[mt][nt][2] + b0;
            Ot[row + 8][col + 1] = acc[mt][nt][3] + b1;
        }
    __syncthreads();

    {
        const int c0v = ot * 64;
        int ww = t >> 1, half = t & 1;
        const float* src = &Ot[ww][half * 32];
        if (b > 0) {
            float* dst = g_vH + (((size_t)(b * 128 + ww)) * 128 + h) * 256 + c0v + half * 32;
            #pragma unroll
            for (int i = 0; i < 8; i++) ((float4*)dst)[i] = ((const float4*)src)[i];
            float* dw = g_vW + ((size_t)(b * 128 + h)) * 32768 + c0v;
            #pragma unroll
            for (int r = 0; r < 8; r++) {
                int e = (t + r * 256) << 2;
                int wI = e >> 6, cI = e & 63;
                *(float4*)(dw + (size_t)wI * 256 + cI) = *(const float4*)&Ot[wI][cI];
            }
        } else {
            float* dst = g_p0 + ((size_t)(h * 128 + ww)) * 320 + 64 + c0v + half * 32;
            #pragma unroll
            for (int i = 0; i < 8; i++) ((float4*)dst)[i] = ((const float4*)src)[i];
        }
    }
}

// ---- deformable bilinear sampling: grid (16384, 2), block 320 ----
__global__ void kern_sample()
{
    const int pt = blockIdx.x, br = blockIdx.y;
    const int k = pt >> 7, pos = pt & 127;
    float px, py;
    if (br == 0) {
        int r = pos + 1;
        px = (-1.0f + k * 0.015625f) + g_dX[r][0];
        py = (-1.0f + r * 0.015625f) + g_dX[r][1];
    } else {
        int ci = pos + 1;
        px = (-1.0f + ci * 0.015625f) + g_dY[ci][0];
        py = (-1.0f + k * 0.015625f) + g_dY[ci][1];
    }
    float fx = (px + 1.0f) * 0.5f * 127.0f;
    float fy = (py + 1.0f) * 0.5f * 127.0f;
    float x0f = floorf(fx), y0f = floorf(fy);
    float wx = fx - x0f, wy = fy - y0f;
    int x0 = (int)x0f, y0 = (int)y0f;
    bool vx0 = (x0 >= 0) && (x0 < 128);
    bool vx1 = (x0 + 1 >= 0) && (x0 + 1 < 128);
    bool vy0 = (y0 >= 0) && (y0 < 128);
    bool vy1 = (y0 + 1 >= 0) && (y0 + 1 < 128);

    const int c = threadIdx.x;
    float acc = 0.f;
    if (vx0 && vy0) acc += g_p0[((size_t)(y0 * 128 + x0)) * 320 + c] * ((1.f - wx) * (1.f - wy));
    if (vx1 && vy0) acc += g_p0[((size_t)(y0 * 128 + x0 + 1)) * 320 + c] * (wx * (1.f - wy));
    if (vx0 && vy1) acc += g_p0[((size_t)((y0 + 1) * 128 + x0)) * 320 + c] * ((1.f - wx) * wy);
    if (vx1 && vy1) acc += g_p0[((size_t)((y0 + 1) * 128 + x0 + 1)) * 320 + c] * (wx * wy);

    size_t lp = (size_t)k * 128 + pos;
    if (br == 0) {
        if (c < 32)      g_qH[lp * 32 + c] = acc;
        else if (c < 64) g_kH[lp * 32 + (c - 32)] = acc;
        else             g_vH[lp * 256 + (c - 64)] = acc;
    } else {
        if (c < 32)      g_qW[lp * 32 + c] = acc;
        else if (c < 64) g_kW[lp * 32 + (c - 32)] = acc;
        else             g_vW[lp * 256 + (c - 64)] = acc;
    }
}

// ---- per-line energy GEMM E = Q @ K^T: grid (512, 2), block 256 ----
__global__ __launch_bounds__(256) void kern_energy()
{
    __shared__ __align__(16) float Qt[32][132];
    __shared__ __align__(16) float Kt[32][132];
    const int l = blockIdx.x, br = blockIdx.y;
    const float* Q = (br ? g_qW : g_qH) + (size_t)l * 4096;
    const float* K = (br ? g_kW : g_kH) + (size_t)l * 4096;
    float* E = (br ? g_EW : g_EH) + (size_t)l * 16384;
    const int t = threadIdx.x;

    #pragma unroll
    for (int r = 0; r < 4; r++) {
        int lin = t + r * 256;
        int p = lin >> 3, c4 = (lin & 7) << 2;
        float4 q = *(const float4*)(Q + (size_t)p * 32 + c4);
        Qt[c4][p] = q.x; Qt[c4 + 1][p] = q.y; Qt[c4 + 2][p] = q.z; Qt[c4 + 3][p] = q.w;
        float4 kk = *(const float4*)(K + (size_t)p * 32 + c4);
        Kt[c4][p] = kk.x; Kt[c4 + 1][p] = kk.y; Kt[c4 + 2][p] = kk.z; Kt[c4 + 3][p] = kk.w;
    }
    __syncthreads();

    const int tj = t & 15, ti = t >> 4;
    const int i0 = ti * 8, j0 = tj * 8;
    ull acc2[8][4];
    #pragma unroll
    for (int u = 0; u < 8; u++)
        #pragma unroll
        for (int v = 0; v < 4; v++) acc2[u][v] = 0ULL;

    #pragma unroll
    for (int c = 0; c < 32; c++) {
        float4 qa = *(const float4*)&Qt[c][i0];
        float4 qb = *(const float4*)&Qt[c][i0 + 4];
        ull ad[8] = {dup2(qa.x), dup2(qa.y), dup2(qa.z), dup2(qa.w),
                     dup2(qb.x), dup2(qb.y), dup2(qb.z), dup2(qb.w)};
        const ull* kp = (const ull*)&Kt[c][j0];
        ull b0 = kp[0], b1 = kp[1], b2 = kp[2], b3 = kp[3];
        #pragma unroll
        for (int u = 0; u < 8; u++) {
            ffma2(acc2[u][0], ad[u], b0);
            ffma2(acc2[u][1], ad[u], b1);
            ffma2(acc2[u][2], ad[u], b2);
            ffma2(acc2[u][3], ad[u], b3);
        }
    }
    #pragma unroll
    for (int u = 0; u < 8; u++) {
        float2 p0 = u2f(acc2[u][0]), p1 = u2f(acc2[u][1]);
        float2 p2 = u2f(acc2[u][2]), p3 = u2f(acc2[u][3]);
        *(float4*)(E + (size_t)(i0 + u) * 128 + j0)     = make_float4(p0.x, p0.y, p1.x, p1.y);
        *(float4*)(E + (size_t)(i0 + u) * 128 + j0 + 4) = make_float4(p2.x, p2.y, p3.x, p3.y);
    }
}

// ---- joint softmax ----
__global__ void kern_softmax()
{
    int gw = (blockIdx.x * blockDim.x + threadIdx.x) >> 5;
    int lane = threadIdx.x & 31;
    if (gw >= 65536) return;
    int b = gw >> 14;
    int rem = gw & 16383;
    int h = rem >> 7, w = rem & 127;
    float* r1 = g_EH + (((size_t)(b * 128 + w)) * 128 + h) * 128;
    float* r2 = g_EW + (((size_t)(b * 128 + h)) * 128 + w) * 128;
    float4 a = *(float4*)(r1 + lane * 4);
    float4 c = *(float4*)(r2 + lane * 4);
    float e1[4] = {a.x, a.y, a.z, a.w};
    float e2[4] = {c.x, c.y, c.z, c.w};
    float m = -INFINITY;
    #pragma unroll
    for (int u = 0; u < 4; u++) {
        if (lane * 4 + u != h) m = fmaxf(m, e1[u]);
        m = fmaxf(m, e2[u]);
    }
    #pragma unroll
    for (int s = 16; s > 0; s >>= 1) m = fmaxf(m, __shfl_xor_sync(0xffffffffu, m, s));
    float sum = 0.f;
    #pragma unroll
    for (int u = 0; u < 4; u++) {
        e1[u] = (lane * 4 + u == h) ? 0.f : __expf(e1[u] - m);
        sum += e1[u];
        e2[u] = __expf(e2[u] - m);
        sum += e2[u];
    }
    #pragma unroll
    for (int s = 16; s > 0; s >>= 1) sum += __shfl_xor_sync(0xffffffffu, sum, s);
    float inv = 1.0f / sum;
    *(float4*)(r1 + lane * 4) = make_float4(e1[0] * inv, e1[1] * inv, e1[2] * inv, e1[3] * inv);
    *(float4*)(r2 + lane * 4) = make_float4(e2[0] * inv, e2[1] * inv, e2[2] * inv, e2[3] * inv);
}

// ---- per-line output GEMM via mma.sync tf32 ----
#define OSM_TOTAL 70656

__global__ __launch_bounds__(256) void kern_out_mma()
{
    extern __shared__ __align__(16) float osm[];
    float* As = osm;             // [2][128][36]
    float* Vs = osm + 9216;      // [2][32][132]
    const int l = blockIdx.x, chf = blockIdx.y, br = blockIdx.z;
    const float* A = (br ? g_EW : g_EH) + (size_t)l * 16384;
    const float* V = (br ? g_vW : g_vH) + (size_t)l * 32768 + chf * 128;
    float* O = (br ? g_rO : g_cO) + (size_t)l * 32768 + chf * 128;
    const int t = threadIdx.x;
    const int w = t >> 5, lane = t & 31;
    const int g = lane >> 2, tig = lane & 3;
    const int kbase = (w >> 1) * 32, cbase = (w & 1) * 64;
    const unsigned as_u = (unsigned)__cvta_generic_to_shared(As);
    const unsigned vs_u = (unsigned)__cvta_generic_to_shared(Vs);

    float acc[2][8][4];
    #pragma unroll
    for (int mt = 0; mt < 2; mt++)
        #pragma unroll
        for (int nt = 0; nt < 8; nt++)
            #pragma unroll
            for (int i = 0; i < 4; i++) acc[mt][nt][i] = 0.f;

    {
        #pragma unroll
        for (int r = 0; r < 4; r++) {
            int idx = t + r * 256;
            int k = idx >> 3, seg = idx & 7;
            cpa16(as_u + (unsigned)((k * 36 + seg * 4) * 4), A + (size_t)k * 128 + seg * 4);
        }
        #pragma unroll
        for (int r = 0; r < 4; r++) {
            int idx = t + r * 256;
            int hh = idx >> 5, seg = idx & 31;
            cpa16(vs_u + (unsigned)((hh * 132 + seg * 4) * 4), V + (size_t)hh * 256 + seg * 4);
        }
        cpa_commit();
    }

    for (int hc = 0; hc < 4; hc++) {
        const int buf = hc & 1;
        cpa_wait<0>();
        __syncthreads();
        if (hc < 3) {
            const int nb = buf ^ 1, hn = (hc + 1) * 32;
            #pragma unroll
            for (int r = 0; r < 4; r++) {
                int idx = t + r * 256;
                int k = idx >> 3, seg = idx & 7;
                cpa16(as_u + (unsigned)((nb * 4608 + k * 36 + seg * 4) * 4),
                      A + (size_t)k * 128 + hn + seg * 4);
            }
            #pragma unroll
            for (int r = 0; r < 4; r++) {
                int idx = t + r * 256;
                int hh = idx >> 5, seg = idx & 31;
                cpa16(vs_u + (unsigned)((nb * 4224 + hh * 132 + seg * 4) * 4),
                      V + (size_t)(hn + hh) * 256 + seg * 4);
            }
            cpa_commit();
        }
        const float* Ab = As + buf * 4608;
        const float* Vb = Vs + buf * 4224;
        #pragma unroll
        for (int hs = 0; hs < 4; hs++) {
            const int hb = hs * 8;
            uint32_t af[2][4];
            #pragma unroll
            for (int mt = 0; mt < 2; mt++) {
                const float* ar = Ab + (kbase + mt * 16 + g) * 36 + hb + tig;
                af[mt][0] = __float_as_uint(ar[0]);
                af[mt][1] = __float_as_uint(ar[8 * 36]);
                af[mt][2] = __float_as_uint(ar[4]);
                af[mt][3] = __float_as_uint(ar[8 * 36 + 4]);
            }
            #pragma unroll
            for (int nt = 0; nt < 8; nt++) {
                const float* vr = Vb + (hb + tig) * 132 + cbase + nt * 8 + g;
                uint32_t bf[2];
                bf[0] = __float_as_uint(vr[0]);
                bf[1] = __float_as_uint(vr[4 * 132]);
                mma_tf32(acc[0][nt], af[0], bf);
                mma_tf32(acc[1][nt], af[1], bf);
            }
        }
    }

    #pragma unroll
    for (int mt = 0; mt < 2; mt++)
        #pragma unroll
        for (int nt = 0; nt < 8; nt++) {
            int row = kbase + mt * 16 + g;
            int col = cbase + nt * 8 + 2 * tig;
            *(float2*)(O + (size_t)row * 256 + col)       = make_float2(acc[mt][nt][0], acc[mt][nt][1]);
            *(float2*)(O + (size_t)(row + 8) * 256 + col) = make_float2(acc[mt][nt][2], acc[mt][nt][3]);
        }
}

// ---- combine ----
__global__ void kern_combine(const float* __restrict__ x, const float* __restrict__ gamma,
                             float* __restrict__ out)
{
    __shared__ __align__(16) float s[32][132];
    const int h = blockIdx.x, ct = blockIdx.y, b = blockIdx.z;
    const int c0 = ct * 32, t = threadIdx.x;
    #pragma unroll
    for (int r = 0; r < 4; r++) {
        int lin = t + r * 256;
        int w = lin >> 3, c4 = (lin & 7) << 2;
        float4 a = *(const float4*)(g_cO + (((size_t)(b * 128 + w)) * 128 + h) * 256 + c0 + c4);
        float4 bb = *(const float4*)(g_rO + (((size_t)(b * 128 + h)) * 128 + w) * 256 + c0 + c4);
        s[c4][w] = a.x + bb.x; s[c4 + 1][w] = a.y + bb.y;
        s[c4 + 2][w] = a.z + bb.z; s[c4 + 3][w] = a.w + bb.w;
    }
    __syncthreads();
    float g = gamma[0];
    #pragma unroll
    for (int r = 0; r < 4; r++) {
        int lin = t + r * 256;
        int c = lin >> 5, w4 = (lin & 31) << 2;
        size_t oidx = (((size_t)b * 256 + c0 + c) * 128 + h) * 128 + w4;
        float4 xv = *(const float4*)(x + oidx);
        float4 o;
        o.x = g * s[c][w4] + xv.x;
        o.y = g * s[c][w4 + 1] + xv.y;
        o.z = g * s[c][w4 + 2] + xv.z;
        o.w = g * s[c][w4 + 3] + xv.w;
        *(float4*)(out + oidx) = o;
    }
}

extern "C" void kernel_launch(void* const* d_in, const int* in_sizes, int n_in,
                              void* d_out, int out_size)
{
    const float* x      = (const float*)d_in[0];
    const float* Wq     = (const float*)d_in[1];
    const float* bq     = (const float*)d_in[2];
    const float* Wk     = (const float*)d_in[3];
    const float* bk     = (const float*)d_in[4];
    const float* Wv     = (const float*)d_in[5];
    const float* bv     = (const float*)d_in[6];
    const float* gamma  = (const float*)d_in[7];
    const float* offs   = (const float*)d_in[8];
    float* out = (float*)d_out;

    cudaFuncSetAttribute(kern_out_mma, cudaFuncAttributeMaxDynamicSharedMemorySize, OSM_TOTAL);
    cudaFuncSetAttribute(kern_projv, cudaFuncAttributeMaxDynamicSharedMemorySize, PSM_TOTAL);

    kern_prep<<<1, 512>>>(offs, out, out_size - 1);
    kern_wt<<<320, 256>>>(Wq, bq, Wk, bk, Wv, bv);
    kern_xT<<<dim3(4, 128, 4), 256>>>(x);
    kern_projqk<<<dim3(128, 1, 4), 256>>>(x);
    kern_projv<<<dim3(128, 4, 4), 256, PSM_TOTAL>>>();
    kern_sample<<<dim3(16384, 2), 320>>>();
    kern_energy<<<dim3(512, 2), 256>>>();
    kern_softmax<<<8192, 256>>>();
    kern_out_mma<<<dim3(512, 2, 2), 256, OSM_TOTAL>>>();
    kern_combine<<<dim3(128, 8, 4), 256>>>(x, gamma, out);
}

// round 13
// speedup vs baseline: 2.7490x; 1.1194x over previous
#include <cuda_runtime.h>
#include <cstdint>
#include <math.h>

#define OFFD 131

__device__ float g_qH[512*128*32];
__device__ float g_kH[512*128*32];
__device__ float g_qW[512*128*32];
__device__ float g_kW[512*128*32];
__device__ float g_vH[512*128*256];
__device__ float g_vW[512*128*256];
__device__ float g_p0[128*128*320];
__device__ float g_EH[512*128*128];
__device__ float g_EW[512*128*128];
__device__ float g_cO[512*128*256];
__device__ float g_rO[512*128*256];
__device__ float g_dX[129][2];
__device__ float g_dY[129][2];
__device__ float g_Wt[256*320];
__device__ float g_bias[320];
__device__ float g_xT[4*128*128*256];   // [b][h][w][c]

typedef unsigned long long ull;

__device__ __forceinline__ void ffma2(ull& d, ull a, ull b) {
    asm("fma.rn.f32x2 %0, %1, %2, %0;" : "+l"(d) : "l"(a), "l"(b));
}
__device__ __forceinline__ ull dup2(float x) {
    ull r; asm("mov.b64 %0, {%1, %1};" : "=l"(r) : "f"(x)); return r;
}
__device__ __forceinline__ float2 u2f(ull v) {
    float2 f; asm("mov.b64 {%0, %1}, %2;" : "=f"(f.x), "=f"(f.y) : "l"(v)); return f;
}
__device__ __forceinline__ void cpa16(unsigned dst, const float* src) {
    asm volatile("cp.async.ca.shared.global [%0], [%1], 16;" :: "r"(dst), "l"(src));
}
__device__ __forceinline__ void cpa_commit() {
    asm volatile("cp.async.commit_group;");
}
template<int N> __device__ __forceinline__ void cpa_wait() {
    asm volatile("cp.async.wait_group %0;" :: "n"(N));
}
__device__ __forceinline__ void mma_tf32(float* d, const uint32_t* a, const uint32_t* b) {
    asm volatile("mma.sync.aligned.m16n8k8.row.col.f32.tf32.tf32.f32 "
                 "{%0,%1,%2,%3}, {%4,%5,%6,%7}, {%8,%9}, {%0,%1,%2,%3};"
                 : "+f"(d[0]), "+f"(d[1]), "+f"(d[2]), "+f"(d[3])
                 : "r"(a[0]), "r"(a[1]), "r"(a[2]), "r"(a[3]), "r"(b[0]), "r"(b[1]));
}
__device__ __forceinline__ uint32_t hi_part(uint32_t u) { return u & 0xFFFFE000u; }
__device__ __forceinline__ uint32_t lo_part(uint32_t u) {
    return __float_as_uint(__uint_as_float(u) - __uint_as_float(u & 0xFFFFE000u));
}

// ---- offset pooling + regloss ----
__global__ void kern_prep(const float* __restrict__ off, float* __restrict__ out, int regIdx)
{
    const int t = threadIdx.x;
    const float inv9 = 1.0f / 9.0f;
    for (int idx = t; idx < 258; idx += 512) {
        int r = idx % 129, ch = idx / 129;
        const float* o = off + ch * OFFD * OFFD;
        float s = 0.f;
        #pragma unroll
        for (int i = 0; i < 3; i++)
            #pragma unroll
            for (int j = 0; j < 3; j++) s += o[(r + i) * OFFD + 64 + j];
        g_dX[r][ch] = s * inv9;
    }
    for (int idx = t; idx < 258; idx += 512) {
        int c = idx % 129, ch = idx / 129;
        const float* o = off + ch * OFFD * OFFD;
        float s = 0.f;
        #pragma unroll
        for (int i = 0; i < 3; i++)
            #pragma unroll
            for (int j = 0; j < 3; j++) s += o[(64 + i) * OFFD + c + j];
        g_dY[c][ch] = s * inv9;
    }
    float s1 = 0.f, s2 = 0.f;
    for (int i = t; i < OFFD * OFFD; i += 512) {
        float d = off[i] - off[OFFD * OFFD + i];
        s1 += d * d;
    }
    for (int i = t; i < 2 * 130 * OFFD; i += 512) {
        int ch = i / (130 * OFFD);
        int rem = i - ch * 130 * OFFD;
        int r = rem / OFFD, c = rem - r * OFFD;
        float d = off[ch * OFFD * OFFD + r * OFFD + c] - off[ch * OFFD * OFFD + (r + 1) * OFFD + c];
        s2 += d * d;
    }
    __shared__ float sh1[512], sh2[512];
    sh1[t] = s1; sh2[t] = s2;
    __syncthreads();
    for (int s = 256; s > 0; s >>= 1) {
        if (t < s) { sh1[t] += sh1[t + s]; sh2[t] += sh2[t + s]; }
        __syncthreads();
    }
    if (t == 0)
        out[regIdx] = sh1[0] / (float)(OFFD * OFFD) + sh2[0] / (float)(2 * 130 * OFFD);
}

// ---- weight transpose ----
__global__ void kern_wt(const float* __restrict__ Wq, const float* __restrict__ bq,
                        const float* __restrict__ Wk, const float* __restrict__ bk,
                        const float* __restrict__ Wv, const float* __restrict__ bv)
{
    const int o = blockIdx.x;
    const int c = threadIdx.x;
    const float* row = (o < 32) ? (Wq + (size_t)o * 256)
                      : (o < 64) ? (Wk + (size_t)(o - 32) * 256)
                                 : (Wv + (size_t)(o - 64) * 256);
    g_Wt[(size_t)c * 320 + o] = row[c];
    if (c == 0)
        g_bias[o] = (o < 32) ? bq[o] : (o < 64) ? bk[o - 32] : bv[o - 64];
}

// ---- x transpose: g_xT[b][h][w][c] = x[b][c][h][w]; grid (4 wt, 128 h, 4 b) ----
__global__ __launch_bounds__(256) void kern_xT(const float* __restrict__ x)
{
    __shared__ float sm[32][33];
    const int wt = blockIdx.x, h = blockIdx.y, b = blockIdx.z;
    const int t = threadIdx.x;
    const int lane = t & 31, row8 = t >> 5;
    const int w0 = wt * 32;
    for (int cc = 0; cc < 8; cc++) {
        #pragma unroll
        for (int r = 0; r < 4; r++) {
            int c = cc * 32 + row8 + r * 8;
            sm[row8 + r * 8][lane] = x[(((size_t)b * 256 + c) * 128 + h) * 128 + w0 + lane];
        }
        __syncthreads();
        #pragma unroll
        for (int r = 0; r < 4; r++) {
            int w = row8 + r * 8;
            g_xT[(((size_t)b * 128 + h) * 128 + w0 + w) * 256 + cc * 32 + lane] = sm[lane][w];
        }
        __syncthreads();
    }
}

#define PSM_TOTAL 54272

// ---- Q/K projection via split-tf32 mma (softmax-safe): grid (h=128, 1, b=4), block 256 ----
__global__ __launch_bounds__(256) void kern_projqk_mma()
{
    extern __shared__ __align__(16) float psm[];
    float* As = psm;             // [2][128][36]
    float* Ws = psm + 9216;      // [2][32][68]
    float (*Ot)[68] = (float (*)[68])psm;

    const int h = blockIdx.x, b = blockIdx.z;
    const int t = threadIdx.x;
    const int w = t >> 5, lane = t & 31;
    const int g = lane >> 2, tig = lane & 3;
    const int mbase = (w >> 1) * 32, nbase = (w & 1) * 32;
    const float* Xr = g_xT + (((size_t)b * 128 + h) * 128) * 256;
    const unsigned as_u = (unsigned)__cvta_generic_to_shared(As);
    const unsigned ws_u = (unsigned)__cvta_generic_to_shared(Ws);

    float acc[2][4][4];
    #pragma unroll
    for (int mt = 0; mt < 2; mt++)
        #pragma unroll
        for (int nt = 0; nt < 4; nt++)
            #pragma unroll
            for (int i = 0; i < 4; i++) acc[mt][nt][i] = 0.f;

    {
        #pragma unroll
        for (int r = 0; r < 4; r++) {
            int idx = t + r * 256;
            int m = idx >> 3, seg = idx & 7;
            cpa16(as_u + (unsigned)((m * 36 + seg * 4) * 4), Xr + (size_t)m * 256 + seg * 4);
        }
        #pragma unroll
        for (int r = 0; r < 2; r++) {
            int idx = t + r * 256;
            int k = idx >> 4, o4 = (idx & 15) << 2;
            cpa16(ws_u + (unsigned)((k * 68 + o4) * 4), g_Wt + (size_t)k * 320 + o4);
        }
        cpa_commit();
    }

    for (int kc = 0; kc < 8; kc++) {
        const int buf = kc & 1;
        cpa_wait<0>();
        __syncthreads();
        if (kc < 7) {
            const int nb = buf ^ 1, kn = (kc + 1) * 32;
            #pragma unroll
            for (int r = 0; r < 4; r++) {
                int idx = t + r * 256;
                int m = idx >> 3, seg = idx & 7;
                cpa16(as_u + (unsigned)((nb * 4608 + m * 36 + seg * 4) * 4),
                      Xr + (size_t)m * 256 + kn + seg * 4);
            }
            #pragma unroll
            for (int r = 0; r < 2; r++) {
                int idx = t + r * 256;
                int k = idx >> 4, o4 = (idx & 15) << 2;
                cpa16(ws_u + (unsigned)((nb * 2176 + k * 68 + o4) * 4),
                      g_Wt + (size_t)(kn + k) * 320 + o4);
            }
            cpa_commit();
        }
        const float* Ab = As + buf * 4608;
        const float* Wb = Ws + buf * 2176;
        #pragma unroll
        for (int hs = 0; hs < 4; hs++) {
            const int kb = hs * 8;
            uint32_t afh[2][4], afl[2][4];
            #pragma unroll
            for (int mt = 0; mt < 2; mt++) {
                const float* ar = Ab + (mbase + mt * 16 + g) * 36 + kb + tig;
                uint32_t a0 = __float_as_uint(ar[0]);
                uint32_t a1 = __float_as_uint(ar[8 * 36]);
                uint32_t a2 = __float_as_uint(ar[4]);
                uint32_t a3 = __float_as_uint(ar[8 * 36 + 4]);
                afh[mt][0] = hi_part(a0); afl[mt][0] = lo_part(a0);
                afh[mt][1] = hi_part(a1); afl[mt][1] = lo_part(a1);
                afh[mt][2] = hi_part(a2); afl[mt][2] = lo_part(a2);
                afh[mt][3] = hi_part(a3); afl[mt][3] = lo_part(a3);
            }
            #pragma unroll
            for (int nt = 0; nt < 4; nt++) {
                const float* br = Wb + (kb + tig) * 68 + nbase + nt * 8 + g;
                uint32_t b0 = __float_as_uint(br[0]);
                uint32_t b1 = __float_as_uint(br[4 * 68]);
                uint32_t bfh[2] = {hi_part(b0), hi_part(b1)};
                uint32_t bfl[2] = {lo_part(b0), lo_part(b1)};
                #pragma unroll
                for (int mt = 0; mt < 2; mt++) {
                    mma_tf32(acc[mt][nt], afh[mt], bfh);
                    mma_tf32(acc[mt][nt], afh[mt], bfl);
                    mma_tf32(acc[mt][nt], afl[mt], bfh);
                }
            }
        }
    }
    __syncthreads();

    #pragma unroll
    for (int mt = 0; mt < 2; mt++)
        #pragma unroll
        for (int nt = 0; nt < 4; nt++) {
            int row = mbase + mt * 16 + g;
            int col = nbase + nt * 8 + 2 * tig;
            float b0 = g_bias[col], b1 = g_bias[col + 1];
            Ot[row][col]     = acc[mt][nt][0] + b0;
            Ot[row][col + 1] = acc[mt][nt][1] + b1;
            Ot[row + 8][col]     = acc[mt][nt][2] + b0;
            Ot[row + 8][col + 1] = acc[mt][nt][3] + b1;
        }
    __syncthreads();

    {
        int ww = t >> 1, half = t & 1;
        const float* src = &Ot[ww][half * 32];
        if (b > 0) {
            float* dst = half ? (g_kH + (((size_t)(b * 128 + ww)) * 128 + h) * 32)
                              : (g_qH + (((size_t)(b * 128 + ww)) * 128 + h) * 32);
            #pragma unroll
            for (int i = 0; i < 8; i++) ((float4*)dst)[i] = ((const float4*)src)[i];
            float* dq = g_qW + ((size_t)(b * 128 + h)) * 4096;
            float* dk = g_kW + ((size_t)(b * 128 + h)) * 4096;
            #pragma unroll
            for (int r = 0; r < 4; r++) {
                int e = (t + r * 256) << 2;
                int wI = e >> 5, cI = e & 31;
                *(float4*)(dq + e) = *(const float4*)&Ot[wI][cI];
                *(float4*)(dk + e) = *(const float4*)&Ot[wI][32 + cI];
            }
        } else {
            float* dst = g_p0 + ((size_t)(h * 128 + ww)) * 320 + half * 32;
            #pragma unroll
            for (int i = 0; i < 8; i++) ((float4*)dst)[i] = ((const float4*)src)[i];
        }
    }
}

// ---- V projection via mma.sync tf32: grid (h=128, ot=4, b=4), block 256 ----
__global__ __launch_bounds__(256) void kern_projv()
{
    extern __shared__ __align__(16) float psm[];
    float* As = psm;             // [2][128][36]
    float* Ws = psm + 9216;      // [2][32][68]
    float (*Ot)[68] = (float (*)[68])psm;

    const int h = blockIdx.x, ot = blockIdx.y, b = blockIdx.z;
    const int t = threadIdx.x;
    const int w = t >> 5, lane = t & 31;
    const int g = lane >> 2, tig = lane & 3;
    const int mbase = (w >> 1) * 32, nbase = (w & 1) * 32;
    const int oc = 64 + ot * 64;
    const float* Xr = g_xT + (((size_t)b * 128 + h) * 128) * 256;
    const unsigned as_u = (unsigned)__cvta_generic_to_shared(As);
    const unsigned ws_u = (unsigned)__cvta_generic_to_shared(Ws);

    float acc[2][4][4];
    #pragma unroll
    for (int mt = 0; mt < 2; mt++)
        #pragma unroll
        for (int nt = 0; nt < 4; nt++)
            #pragma unroll
            for (int i = 0; i < 4; i++) acc[mt][nt][i] = 0.f;

    {
        #pragma unroll
        for (int r = 0; r < 4; r++) {
            int idx = t + r * 256;
            int m = idx >> 3, seg = idx & 7;
            cpa16(as_u + (unsigned)((m * 36 + seg * 4) * 4), Xr + (size_t)m * 256 + seg * 4);
        }
        #pragma unroll
        for (int r = 0; r < 2; r++) {
            int idx = t + r * 256;
            int k = idx >> 4, o4 = (idx & 15) << 2;
            cpa16(ws_u + (unsigned)((k * 68 + o4) * 4), g_Wt + (size_t)k * 320 + oc + o4);
        }
        cpa_commit();
    }

    for (int kc = 0; kc < 8; kc++) {
        const int buf = kc & 1;
        cpa_wait<0>();
        __syncthreads();
        if (kc < 7) {
            const int nb = buf ^ 1, kn = (kc + 1) * 32;
            #pragma unroll
            for (int r = 0; r < 4; r++) {
                int idx = t + r * 256;
                int m = idx >> 3, seg = idx & 7;
                cpa16(as_u + (unsigned)((nb * 4608 + m * 36 + seg * 4) * 4),
                      Xr + (size_t)m * 256 + kn + seg * 4);
            }
            #pragma unroll
            for (int r = 0; r < 2; r++) {
                int idx = t + r * 256;
                int k = idx >> 4, o4 = (idx & 15) << 2;
                cpa16(ws_u + (unsigned)((nb * 2176 + k * 68 + o4) * 4),
                      g_Wt + (size_t)(kn + k) * 320 + oc + o4);
            }
            cpa_commit();
        }
        const float* Ab = As + buf * 4608;
        const float* Wb = Ws + buf * 2176;
        #pragma unroll
        for (int hs = 0; hs < 4; hs++) {
            const int kb = hs * 8;
            uint32_t af[2][4];
            #pragma unroll
            for (int mt = 0; mt < 2; mt++) {
                const float* ar = Ab + (mbase + mt * 16 + g) * 36 + kb + tig;
                af[mt][0] = __float_as_uint(ar[0]);
                af[mt][1] = __float_as_uint(ar[8 * 36]);
                af[mt][2] = __float_as_uint(ar[4]);
                af[mt][3] = __float_as_uint(ar[8 * 36 + 4]);
            }
            #pragma unroll
            for (int nt = 0; nt < 4; nt++) {
                const float* br = Wb + (kb + tig) * 68 + nbase + nt * 8 + g;
                uint32_t bf[2];
                bf[0] = __float_as_uint(br[0]);
                bf[1] = __float_as_uint(br[4 * 68]);
                mma_tf32(acc[0][nt], af[0], bf);
                mma_tf32(acc[1][nt], af[1], bf);
            }
        }
    }
    __syncthreads();

    #pragma unroll
    for (int mt = 0; mt < 2; mt++)
        #pragma unroll
        for (int nt = 0; nt < 4; nt++) {
            int row = mbase + mt * 16 + g;
            int col = nbase + nt * 8 + 2 * tig;
            float b0 = g_bias[oc + col], b1 = g_bias[oc + col + 1];
            Ot[row][col]     = acc[mt][nt][0] + b0;
            Ot[row][col + 1] = acc[mt][nt][1] + b1;
            Ot[row + 8][col]     = acc[mt][nt][2] + b0;
            Ot[row + 8][col + 1] = acc[mt][nt][3] + b1;
        }
    __syncthreads();

    {
        const int c0v = ot * 64;
        int ww = t >> 1, half = t & 1;
        const float* src = &Ot[ww][half * 32];
        if (b > 0) {
            float* dst = g_vH + (((size_t)(b * 128 + ww)) * 128 + h) * 256 + c0v + half * 32;
            #pragma unroll
            for (int i = 0; i < 8; i++) ((float4*)dst)[i] = ((const float4*)src)[i];
            float* dw = g_vW + ((size_t)(b * 128 + h)) * 32768 + c0v;
            #pragma unroll
            for (int r = 0; r < 8; r++) {
                int e = (t + r * 256) << 2;
                int wI = e >> 6, cI = e & 63;
                *(float4*)(dw + (size_t)wI * 256 + cI) = *(const float4*)&Ot[wI][cI];
            }
        } else {
            float* dst = g_p0 + ((size_t)(h * 128 + ww)) * 320 + 64 + c0v + half * 32;
            #pragma unroll
            for (int i = 0; i < 8; i++) ((float4*)dst)[i] = ((const float4*)src)[i];
        }
    }
}

// ---- deformable bilinear sampling: grid (16384, 2), block 320 ----
__global__ void kern_sample()
{
    const int pt = blockIdx.x, br = blockIdx.y;
    const int k = pt >> 7, pos = pt & 127;
    float px, py;
    if (br == 0) {
        int r = pos + 1;
        px = (-1.0f + k * 0.015625f) + g_dX[r][0];
        py = (-1.0f + r * 0.015625f) + g_dX[r][1];
    } else {
        int ci = pos + 1;
        px = (-1.0f + ci * 0.015625f) + g_dY[ci][0];
        py = (-1.0f + k * 0.015625f) + g_dY[ci][1];
    }
    float fx = (px + 1.0f) * 0.5f * 127.0f;
    float fy = (py + 1.0f) * 0.5f * 127.0f;
    float x0f = floorf(fx), y0f = floorf(fy);
    float wx = fx - x0f, wy = fy - y0f;
    int x0 = (int)x0f, y0 = (int)y0f;
    bool vx0 = (x0 >= 0) && (x0 < 128);
    bool vx1 = (x0 + 1 >= 0) && (x0 + 1 < 128);
    bool vy0 = (y0 >= 0) && (y0 < 128);
    bool vy1 = (y0 + 1 >= 0) && (y0 + 1 < 128);

    const int c = threadIdx.x;
    float acc = 0.f;
    if (vx0 && vy0) acc += g_p0[((size_t)(y0 * 128 + x0)) * 320 + c] * ((1.f - wx) * (1.f - wy));
    if (vx1 && vy0) acc += g_p0[((size_t)(y0 * 128 + x0 + 1)) * 320 + c] * (wx * (1.f - wy));
    if (vx0 && vy1) acc += g_p0[((size_t)((y0 + 1) * 128 + x0)) * 320 + c] * ((1.f - wx) * wy);
    if (vx1 && vy1) acc += g_p0[((size_t)((y0 + 1) * 128 + x0 + 1)) * 320 + c] * (wx * wy);

    size_t lp = (size_t)k * 128 + pos;
    if (br == 0) {
        if (c < 32)      g_qH[lp * 32 + c] = acc;
        else if (c < 64) g_kH[lp * 32 + (c - 32)] = acc;
        else             g_vH[lp * 256 + (c - 64)] = acc;
    } else {
        if (c < 32)      g_qW[lp * 32 + c] = acc;
        else if (c < 64) g_kW[lp * 32 + (c - 32)] = acc;
        else             g_vW[lp * 256 + (c - 64)] = acc;
    }
}

// ---- per-line energy GEMM E = Q @ K^T: grid (512, 2), block 256 ----
__global__ __launch_bounds__(256) void kern_energy()
{
    __shared__ __align__(16) float Qt[32][132];
    __shared__ __align__(16) float Kt[32][132];
    const int l = blockIdx.x, br = blockIdx.y;
    const float* Q = (br ? g_qW : g_qH) + (size_t)l * 4096;
    const float* K = (br ? g_kW : g_kH) + (size_t)l * 4096;
    float* E = (br ? g_EW : g_EH) + (size_t)l * 16384;
    const int t = threadIdx.x;

    #pragma unroll
    for (int r = 0; r < 4; r++) {
        int lin = t + r * 256;
        int p = lin >> 3, c4 = (lin & 7) << 2;
        float4 q = *(const float4*)(Q + (size_t)p * 32 + c4);
        Qt[c4][p] = q.x; Qt[c4 + 1][p] = q.y; Qt[c4 + 2][p] = q.z; Qt[c4 + 3][p] = q.w;
        float4 kk = *(const float4*)(K + (size_t)p * 32 + c4);
        Kt[c4][p] = kk.x; Kt[c4 + 1][p] = kk.y; Kt[c4 + 2][p] = kk.z; Kt[c4 + 3][p] = kk.w;
    }
    __syncthreads();

    const int tj = t & 15, ti = t >> 4;
    const int i0 = ti * 8, j0 = tj * 8;
    ull acc2[8][4];
    #pragma unroll
    for (int u = 0; u < 8; u++)
        #pragma unroll
        for (int v = 0; v < 4; v++) acc2[u][v] = 0ULL;

    #pragma unroll
    for (int c = 0; c < 32; c++) {
        float4 qa = *(const float4*)&Qt[c][i0];
        float4 qb = *(const float4*)&Qt[c][i0 + 4];
        ull ad[8] = {dup2(qa.x), dup2(qa.y), dup2(qa.z), dup2(qa.w),
                     dup2(qb.x), dup2(qb.y), dup2(qb.z), dup2(qb.w)};
        const ull* kp = (const ull*)&Kt[c][j0];
        ull b0 = kp[0], b1 = kp[1], b2 = kp[2], b3 = kp[3];
        #pragma unroll
        for (int u = 0; u < 8; u++) {
            ffma2(acc2[u][0], ad[u], b0);
            ffma2(acc2[u][1], ad[u], b1);
            ffma2(acc2[u][2], ad[u], b2);
            ffma2(acc2[u][3], ad[u], b3);
        }
    }
    #pragma unroll
    for (int u = 0; u < 8; u++) {
        float2 p0 = u2f(acc2[u][0]), p1 = u2f(acc2[u][1]);
        float2 p2 = u2f(acc2[u][2]), p3 = u2f(acc2[u][3]);
        *(float4*)(E + (size_t)(i0 + u) * 128 + j0)     = make_float4(p0.x, p0.y, p1.x, p1.y);
        *(float4*)(E + (size_t)(i0 + u) * 128 + j0 + 4) = make_float4(p2.x, p2.y, p3.x, p3.y);
    }
}

// ---- joint softmax ----
__global__ void kern_softmax()
{
    int gw = (blockIdx.x * blockDim.x + threadIdx.x) >> 5;
    int lane = threadIdx.x & 31;
    if (gw >= 65536) return;
    int b = gw >> 14;
    int rem = gw & 16383;
    int h = rem >> 7, w = rem & 127;
    float* r1 = g_EH + (((size_t)(b * 128 + w)) * 128 + h) * 128;
    float* r2 = g_EW + (((size_t)(b * 128 + h)) * 128 + w) * 128;
    float4 a = *(float4*)(r1 + lane * 4);
    float4 c = *(float4*)(r2 + lane * 4);
    float e1[4] = {a.x, a.y, a.z, a.w};
    float e2[4] = {c.x, c.y, c.z, c.w};
    float m = -INFINITY;
    #pragma unroll
    for (int u = 0; u < 4; u++) {
        if (lane * 4 + u != h) m = fmaxf(m, e1[u]);
        m = fmaxf(m, e2[u]);
    }
    #pragma unroll
    for (int s = 16; s > 0; s >>= 1) m = fmaxf(m, __shfl_xor_sync(0xffffffffu, m, s));
    float sum = 0.f;
    #pragma unroll
    for (int u = 0; u < 4; u++) {
        e1[u] = (lane * 4 + u == h) ? 0.f : __expf(e1[u] - m);
        sum += e1[u];
        e2[u] = __expf(e2[u] - m);
        sum += e2[u];
    }
    #pragma unroll
    for (int s = 16; s > 0; s >>= 1) sum += __shfl_xor_sync(0xffffffffu, sum, s);
    float inv = 1.0f / sum;
    *(float4*)(r1 + lane * 4) = make_float4(e1[0] * inv, e1[1] * inv, e1[2] * inv, e1[3] * inv);
    *(float4*)(r2 + lane * 4) = make_float4(e2[0] * inv, e2[1] * inv, e2[2] * inv, e2[3] * inv);
}

// ---- per-line output GEMM via mma.sync tf32 ----
#define OSM_TOTAL 70656

__global__ __launch_bounds__(256) void kern_out_mma()
{
    extern __shared__ __align__(16) float osm[];
    float* As = osm;             // [2][128][36]
    float* Vs = osm + 9216;      // [2][32][132]
    const int l = blockIdx.x, chf = blockIdx.y, br = blockIdx.z;
    const float* A = (br ? g_EW : g_EH) + (size_t)l * 16384;
    const float* V = (br ? g_vW : g_vH) + (size_t)l * 32768 + chf * 128;
    float* O = (br ? g_rO : g_cO) + (size_t)l * 32768 + chf * 128;
    const int t = threadIdx.x;
    const int w = t >> 5, lane = t & 31;
    const int g = lane >> 2, tig = lane & 3;
    const int kbase = (w >> 1) * 32, cbase = (w & 1) * 64;
    const unsigned as_u = (unsigned)__cvta_generic_to_shared(As);
    const unsigned vs_u = (unsigned)__cvta_generic_to_shared(Vs);

    float acc[2][8][4];
    #pragma unroll
    for (int mt = 0; mt < 2; mt++)
        #pragma unroll
        for (int nt = 0; nt < 8; nt++)
            #pragma unroll
            for (int i = 0; i < 4; i++) acc[mt][nt][i] = 0.f;

    {
        #pragma unroll
        for (int r = 0; r < 4; r++) {
            int idx = t + r * 256;
            int k = idx >> 3, seg = idx & 7;
            cpa16(as_u + (unsigned)((k * 36 + seg * 4) * 4), A + (size_t)k * 128 + seg * 4);
        }
        #pragma unroll
        for (int r = 0; r < 4; r++) {
            int idx = t + r * 256;
            int hh = idx >> 5, seg = idx & 31;
            cpa16(vs_u + (unsigned)((hh * 132 + seg * 4) * 4), V + (size_t)hh * 256 + seg * 4);
        }
        cpa_commit();
    }

    for (int hc = 0; hc < 4; hc++) {
        const int buf = hc & 1;
        cpa_wait<0>();
        __syncthreads();
        if (hc < 3) {
            const int nb = buf ^ 1, hn = (hc + 1) * 32;
            #pragma unroll
            for (int r = 0; r < 4; r++) {
                int idx = t + r * 256;
                int k = idx >> 3, seg = idx & 7;
                cpa16(as_u + (unsigned)((nb * 4608 + k * 36 + seg * 4) * 4),
                      A + (size_t)k * 128 + hn + seg * 4);
            }
            #pragma unroll
            for (int r = 0; r < 4; r++) {
                int idx = t + r * 256;
                int hh = idx >> 5, seg = idx & 31;
                cpa16(vs_u + (unsigned)((nb * 4224 + hh * 132 + seg * 4) * 4),
                      V + (size_t)(hn + hh) * 256 + seg * 4);
            }
            cpa_commit();
        }
        const float* Ab = As + buf * 4608;
        const float* Vb = Vs + buf * 4224;
        #pragma unroll
        for (int hs = 0; hs < 4; hs++) {
            const int hb = hs * 8;
            uint32_t af[2][4];
            #pragma unroll
            for (int mt = 0; mt < 2; mt++) {
                const float* ar = Ab + (kbase + mt * 16 + g) * 36 + hb + tig;
                af[mt][0] = __float_as_uint(ar[0]);
                af[mt][1] = __float_as_uint(ar[8 * 36]);
                af[mt][2] = __float_as_uint(ar[4]);
                af[mt][3] = __float_as_uint(ar[8 * 36 + 4]);
            }
            #pragma unroll
            for (int nt = 0; nt < 8; nt++) {
                const float* vr = Vb + (hb + tig) * 132 + cbase + nt * 8 + g;
                uint32_t bf[2];
                bf[0] = __float_as_uint(vr[0]);
                bf[1] = __float_as_uint(vr[4 * 132]);
                mma_tf32(acc[0][nt], af[0], bf);
                mma_tf32(acc[1][nt], af[1], bf);
            }
        }
    }

    #pragma unroll
    for (int mt = 0; mt < 2; mt++)
        #pragma unroll
        for (int nt = 0; nt < 8; nt++) {
            int row = kbase + mt * 16 + g;
            int col = cbase + nt * 8 + 2 * tig;
            *(float2*)(O + (size_t)row * 256 + col)       = make_float2(acc[mt][nt][0], acc[mt][nt][1]);
            *(float2*)(O + (size_t)(row + 8) * 256 + col) = make_float2(acc[mt][nt][2], acc[mt][nt][3]);
        }
}

// ---- combine ----
__global__ void kern_combine(const float* __restrict__ x, const float* __restrict__ gamma,
                             float* __restrict__ out)
{
    __shared__ __align__(16) float s[32][132];
    const int h = blockIdx.x, ct = blockIdx.y, b = blockIdx.z;
    const int c0 = ct * 32, t = threadIdx.x;
    #pragma unroll
    for (int r = 0; r < 4; r++) {
        int lin = t + r * 256;
        int w = lin >> 3, c4 = (lin & 7) << 2;
        float4 a = *(const float4*)(g_cO + (((size_t)(b * 128 + w)) * 128 + h) * 256 + c0 + c4);
        float4 bb = *(const float4*)(g_rO + (((size_t)(b * 128 + h)) * 128 + w) * 256 + c0 + c4);
        s[c4][w] = a.x + bb.x; s[c4 + 1][w] = a.y + bb.y;
        s[c4 + 2][w] = a.z + bb.z; s[c4 + 3][w] = a.w + bb.w;
    }
    __syncthreads();
    float g = gamma[0];
    #pragma unroll
    for (int r = 0; r < 4; r++) {
        int lin = t + r * 256;
        int c = lin >> 5, w4 = (lin & 31) << 2;
        size_t oidx = (((size_t)b * 256 + c0 + c) * 128 + h) * 128 + w4;
        float4 xv = *(const float4*)(x + oidx);
        float4 o;
        o.x = g * s[c][w4] + xv.x;
        o.y = g * s[c][w4 + 1] + xv.y;
        o.z = g * s[c][w4 + 2] + xv.z;
        o.w = g * s[c][w4 + 3] + xv.w;
        *(float4*)(out + oidx) = o;
    }
}

extern "C" void kernel_launch(void* const* d_in, const int* in_sizes, int n_in,
                              void* d_out, int out_size)
{
    const float* x      = (const float*)d_in[0];
    const float* Wq     = (const float*)d_in[1];
    const float* bq     = (const float*)d_in[2];
    const float* Wk     = (const float*)d_in[3];
    const float* bk     = (const float*)d_in[4];
    const float* Wv     = (const float*)d_in[5];
    const float* bv     = (const float*)d_in[6];
    const float* gamma  = (const float*)d_in[7];
    const float* offs   = (const float*)d_in[8];
    float* out = (float*)d_out;

    cudaFuncSetAttribute(kern_out_mma, cudaFuncAttributeMaxDynamicSharedMemorySize, OSM_TOTAL);
    cudaFuncSetAttribute(kern_projv, cudaFuncAttributeMaxDynamicSharedMemorySize, PSM_TOTAL);
    cudaFuncSetAttribute(kern_projqk_mma, cudaFuncAttributeMaxDynamicSharedMemorySize, PSM_TOTAL);

    kern_prep<<<1, 512>>>(offs, out, out_size - 1);
    kern_wt<<<320, 256>>>(Wq, bq, Wk, bk, Wv, bv);
    kern_xT<<<dim3(4, 128, 4), 256>>>(x);
    kern_projqk_mma<<<dim3(128, 1, 4), 256, PSM_TOTAL>>>();
    kern_projv<<<dim3(128, 4, 4), 256, PSM_TOTAL>>>();
    kern_sample<<<dim3(16384, 2), 320>>>();
    kern_energy<<<dim3(512, 2), 256>>>();
    kern_softmax<<<8192, 256>>>();
    kern_out_mma<<<dim3(512, 2, 2), 256, OSM_TOTAL>>>();
    kern_combine<<<dim3(128, 8, 4), 256>>>(x, gamma, out);
}

// round 14
// speedup vs baseline: 2.8365x; 1.0318x over previous
#include <cuda_runtime.h>
#include <cstdint>
#include <math.h>

#define OFFD 131

__device__ float g_qH[512*128*32];
__device__ float g_kH[512*128*32];
__device__ float g_qW[512*128*32];
__device__ float g_kW[512*128*32];
__device__ float g_vH[512*128*256];
__device__ float g_vW[512*128*256];
__device__ float g_p0[128*128*320];
__device__ float g_EH[512*128*128];
__device__ float g_EW[512*128*128];
__device__ float g_cO[512*128*256];
__device__ float g_rO[512*128*256];
__device__ float g_dX[129][2];
__device__ float g_dY[129][2];
__device__ float g_Wt[256*320];
__device__ float g_bias[320];
__device__ float g_xT[4*128*128*256];   // [b][h][w][c]

typedef unsigned long long ull;

__device__ __forceinline__ void ffma2(ull& d, ull a, ull b) {
    asm("fma.rn.f32x2 %0, %1, %2, %0;" : "+l"(d) : "l"(a), "l"(b));
}
__device__ __forceinline__ ull dup2(float x) {
    ull r; asm("mov.b64 %0, {%1, %1};" : "=l"(r) : "f"(x)); return r;
}
__device__ __forceinline__ float2 u2f(ull v) {
    float2 f; asm("mov.b64 {%0, %1}, %2;" : "=f"(f.x), "=f"(f.y) : "l"(v)); return f;
}
__device__ __forceinline__ void cpa16(unsigned dst, const float* src) {
    asm volatile("cp.async.ca.shared.global [%0], [%1], 16;" :: "r"(dst), "l"(src));
}
__device__ __forceinline__ void cpa_commit() {
    asm volatile("cp.async.commit_group;");
}
template<int N> __device__ __forceinline__ void cpa_wait() {
    asm volatile("cp.async.wait_group %0;" :: "n"(N));
}
__device__ __forceinline__ void mma_tf32(float* d, const uint32_t* a, const uint32_t* b) {
    asm volatile("mma.sync.aligned.m16n8k8.row.col.f32.tf32.tf32.f32 "
                 "{%0,%1,%2,%3}, {%4,%5,%6,%7}, {%8,%9}, {%0,%1,%2,%3};"
                 : "+f"(d[0]), "+f"(d[1]), "+f"(d[2]), "+f"(d[3])
                 : "r"(a[0]), "r"(a[1]), "r"(a[2]), "r"(a[3]), "r"(b[0]), "r"(b[1]));
}
__device__ __forceinline__ uint32_t hi_part(uint32_t u) { return u & 0xFFFFE000u; }
__device__ __forceinline__ uint32_t lo_part(uint32_t u) {
    return __float_as_uint(__uint_as_float(u) - __uint_as_float(u & 0xFFFFE000u));
}

// ---- offset pooling + regloss ----
__global__ void kern_prep(const float* __restrict__ off, float* __restrict__ out, int regIdx)
{
    const int t = threadIdx.x;
    const float inv9 = 1.0f / 9.0f;
    for (int idx = t; idx < 258; idx += 512) {
        int r = idx % 129, ch = idx / 129;
        const float* o = off + ch * OFFD * OFFD;
        float s = 0.f;
        #pragma unroll
        for (int i = 0; i < 3; i++)
            #pragma unroll
            for (int j = 0; j < 3; j++) s += o[(r + i) * OFFD + 64 + j];
        g_dX[r][ch] = s * inv9;
    }
    for (int idx = t; idx < 258; idx += 512) {
        int c = idx % 129, ch = idx / 129;
        const float* o = off + ch * OFFD * OFFD;
        float s = 0.f;
        #pragma unroll
        for (int i = 0; i < 3; i++)
            #pragma unroll
            for (int j = 0; j < 3; j++) s += o[(64 + i) * OFFD + c + j];
        g_dY[c][ch] = s * inv9;
    }
    float s1 = 0.f, s2 = 0.f;
    for (int i = t; i < OFFD * OFFD; i += 512) {
        float d = off[i] - off[OFFD * OFFD + i];
        s1 += d * d;
    }
    for (int i = t; i < 2 * 130 * OFFD; i += 512) {
        int ch = i / (130 * OFFD);
        int rem = i - ch * 130 * OFFD;
        int r = rem / OFFD, c = rem - r * OFFD;
        float d = off[ch * OFFD * OFFD + r * OFFD + c] - off[ch * OFFD * OFFD + (r + 1) * OFFD + c];
        s2 += d * d;
    }
    __shared__ float sh1[512], sh2[512];
    sh1[t] = s1; sh2[t] = s2;
    __syncthreads();
    for (int s = 256; s > 0; s >>= 1) {
        if (t < s) { sh1[t] += sh1[t + s]; sh2[t] += sh2[t + s]; }
        __syncthreads();
    }
    if (t == 0)
        out[regIdx] = sh1[0] / (float)(OFFD * OFFD) + sh2[0] / (float)(2 * 130 * OFFD);
}

// ---- weight transpose ----
__global__ void kern_wt(const float* __restrict__ Wq, const float* __restrict__ bq,
                        const float* __restrict__ Wk, const float* __restrict__ bk,
                        const float* __restrict__ Wv, const float* __restrict__ bv)
{
    const int o = blockIdx.x;
    const int c = threadIdx.x;
    const float* row = (o < 32) ? (Wq + (size_t)o * 256)
                      : (o < 64) ? (Wk + (size_t)(o - 32) * 256)
                                 : (Wv + (size_t)(o - 64) * 256);
    g_Wt[(size_t)c * 320 + o] = row[c];
    if (c == 0)
        g_bias[o] = (o < 32) ? bq[o] : (o < 64) ? bk[o - 32] : bv[o - 64];
}

// ---- x transpose: g_xT[b][h][w][c] = x[b][c][h][w]; grid (4 wt, 128 h, 4 b) ----
__global__ __launch_bounds__(256) void kern_xT(const float* __restrict__ x)
{
    __shared__ float sm[32][33];
    const int wt = blockIdx.x, h = blockIdx.y, b = blockIdx.z;
    const int t = threadIdx.x;
    const int lane = t & 31, row8 = t >> 5;
    const int w0 = wt * 32;
    for (int cc = 0; cc < 8; cc++) {
        #pragma unroll
        for (int r = 0; r < 4; r++) {
            int c = cc * 32 + row8 + r * 8;
            sm[row8 + r * 8][lane] = x[(((size_t)b * 256 + c) * 128 + h) * 128 + w0 + lane];
        }
        __syncthreads();
        #pragma unroll
        for (int r = 0; r < 4; r++) {
            int w = row8 + r * 8;
            g_xT[(((size_t)b * 128 + h) * 128 + w0 + w) * 256 + cc * 32 + lane] = sm[lane][w];
        }
        __syncthreads();
    }
}

// smem: As[2][128][36] (36864 B) + Ws[2][32][72] (18432 B) = 55296 B
#define PSM_TOTAL 55296

// ---- Q/K projection via split-tf32 mma (softmax-safe): grid (h=128, 1, b=4), block 256 ----
__global__ __launch_bounds__(256) void kern_projqk_mma()
{
    extern __shared__ __align__(16) float psm[];
    float* As = psm;             // [2][128][36]
    float* Ws = psm + 9216;      // [2][32][72]
    float (*Ot)[68] = (float (*)[68])psm;

    const int h = blockIdx.x, b = blockIdx.z;
    const int t = threadIdx.x;
    const int w = t >> 5, lane = t & 31;
    const int g = lane >> 2, tig = lane & 3;
    const int mbase = (w >> 1) * 32, nbase = (w & 1) * 32;
    const float* Xr = g_xT + (((size_t)b * 128 + h) * 128) * 256;
    const unsigned as_u = (unsigned)__cvta_generic_to_shared(As);
    const unsigned ws_u = (unsigned)__cvta_generic_to_shared(Ws);

    float acc[2][4][4];
    #pragma unroll
    for (int mt = 0; mt < 2; mt++)
        #pragma unroll
        for (int nt = 0; nt < 4; nt++)
            #pragma unroll
            for (int i = 0; i < 4; i++) acc[mt][nt][i] = 0.f;

    {
        #pragma unroll
        for (int r = 0; r < 4; r++) {
            int idx = t + r * 256;
            int m = idx >> 3, seg = idx & 7;
            cpa16(as_u + (unsigned)((m * 36 + seg * 4) * 4), Xr + (size_t)m * 256 + seg * 4);
        }
        #pragma unroll
        for (int r = 0; r < 2; r++) {
            int idx = t + r * 256;
            int k = idx >> 4, o4 = (idx & 15) << 2;
            cpa16(ws_u + (unsigned)((k * 72 + o4) * 4), g_Wt + (size_t)k * 320 + o4);
        }
        cpa_commit();
    }

    for (int kc = 0; kc < 8; kc++) {
        const int buf = kc & 1;
        cpa_wait<0>();
        __syncthreads();
        if (kc < 7) {
            const int nb = buf ^ 1, kn = (kc + 1) * 32;
            #pragma unroll
            for (int r = 0; r < 4; r++) {
                int idx = t + r * 256;
                int m = idx >> 3, seg = idx & 7;
                cpa16(as_u + (unsigned)((nb * 4608 + m * 36 + seg * 4) * 4),
                      Xr + (size_t)m * 256 + kn + seg * 4);
            }
            #pragma unroll
            for (int r = 0; r < 2; r++) {
                int idx = t + r * 256;
                int k = idx >> 4, o4 = (idx & 15) << 2;
                cpa16(ws_u + (unsigned)((nb * 2304 + k * 72 + o4) * 4),
                      g_Wt + (size_t)(kn + k) * 320 + o4);
            }
            cpa_commit();
        }
        const float* Ab = As + buf * 4608;
        const float* Wb = Ws + buf * 2304;
        #pragma unroll
        for (int hs = 0; hs < 4; hs++) {
            const int kb = hs * 8;
            uint32_t afh[2][4], afl[2][4];
            #pragma unroll
            for (int mt = 0; mt < 2; mt++) {
                const float* ar = Ab + (mbase + mt * 16 + g) * 36 + kb + tig;
                uint32_t a0 = __float_as_uint(ar[0]);
                uint32_t a1 = __float_as_uint(ar[8 * 36]);
                uint32_t a2 = __float_as_uint(ar[4]);
                uint32_t a3 = __float_as_uint(ar[8 * 36 + 4]);
                afh[mt][0] = hi_part(a0); afl[mt][0] = lo_part(a0);
                afh[mt][1] = hi_part(a1); afl[mt][1] = lo_part(a1);
                afh[mt][2] = hi_part(a2); afl[mt][2] = lo_part(a2);
                afh[mt][3] = hi_part(a3); afl[mt][3] = lo_part(a3);
            }
            #pragma unroll
            for (int nt = 0; nt < 4; nt++) {
                const float* br = Wb + (kb + tig) * 72 + nbase + nt * 8 + g;
                uint32_t b0 = __float_as_uint(br[0]);
                uint32_t b1 = __float_as_uint(br[4 * 72]);
                uint32_t bfh[2] = {hi_part(b0), hi_part(b1)};
                uint32_t bfl[2] = {lo_part(b0), lo_part(b1)};
                #pragma unroll
                for (int mt = 0; mt < 2; mt++) {
                    mma_tf32(acc[mt][nt], afh[mt], bfh);
                    mma_tf32(acc[mt][nt], afh[mt], bfl);
                    mma_tf32(acc[mt][nt], afl[mt], bfh);
                }
            }
        }
    }
    __syncthreads();

    #pragma unroll
    for (int mt = 0; mt < 2; mt++)
        #pragma unroll
        for (int nt = 0; nt < 4; nt++) {
            int row = mbase + mt * 16 + g;
            int col = nbase + nt * 8 + 2 * tig;
            float b0 = g_bias[col], b1 = g_bias[col + 1];
            Ot[row][col]     = acc[mt][nt][0] + b0;
            Ot[row][col + 1] = acc[mt][nt][1] + b1;
            Ot[row + 8][col]     = acc[mt][nt][2] + b0;
            Ot[row + 8][col + 1] = acc[mt][nt][3] + b1;
        }
    __syncthreads();

    {
        int ww = t >> 1, half = t & 1;
        const float* src = &Ot[ww][half * 32];
        if (b > 0) {
            float* dst = half ? (g_kH + (((size_t)(b * 128 + ww)) * 128 + h) * 32)
                              : (g_qH + (((size_t)(b * 128 + ww)) * 128 + h) * 32);
            #pragma unroll
            for (int i = 0; i < 8; i++) ((float4*)dst)[i] = ((const float4*)src)[i];
            float* dq = g_qW + ((size_t)(b * 128 + h)) * 4096;
            float* dk = g_kW + ((size_t)(b * 128 + h)) * 4096;
            #pragma unroll
            for (int r = 0; r < 4; r++) {
                int e = (t + r * 256) << 2;
                int wI = e >> 5, cI = e & 31;
                *(float4*)(dq + e) = *(const float4*)&Ot[wI][cI];
                *(float4*)(dk + e) = *(const float4*)&Ot[wI][32 + cI];
            }
        } else {
            float* dst = g_p0 + ((size_t)(h * 128 + ww)) * 320 + half * 32;
            #pragma unroll
            for (int i = 0; i < 8; i++) ((float4*)dst)[i] = ((const float4*)src)[i];
        }
    }
}

// ---- V projection via mma.sync tf32: grid (h=128, ot=4, b=4), block 256 ----
__global__ __launch_bounds__(256) void kern_projv()
{
    extern __shared__ __align__(16) float psm[];
    float* As = psm;             // [2][128][36]
    float* Ws = psm + 9216;      // [2][32][72]
    float (*Ot)[68] = (float (*)[68])psm;

    const int h = blockIdx.x, ot = blockIdx.y, b = blockIdx.z;
    const int t = threadIdx.x;
    const int w = t >> 5, lane = t & 31;
    const int g = lane >> 2, tig = lane & 3;
    const int mbase = (w >> 1) * 32, nbase = (w & 1) * 32;
    const int oc = 64 + ot * 64;
    const float* Xr = g_xT + (((size_t)b * 128 + h) * 128) * 256;
    const unsigned as_u = (unsigned)__cvta_generic_to_shared(As);
    const unsigned ws_u = (unsigned)__cvta_generic_to_shared(Ws);

    float acc[2][4][4];
    #pragma unroll
    for (int mt = 0; mt < 2; mt++)
        #pragma unroll
        for (int nt = 0; nt < 4; nt++)
            #pragma unroll
            for (int i = 0; i < 4; i++) acc[mt][nt][i] = 0.f;

    {
        #pragma unroll
        for (int r = 0; r < 4; r++) {
            int idx = t + r * 256;
            int m = idx >> 3, seg = idx & 7;
            cpa16(as_u + (unsigned)((m * 36 + seg * 4) * 4), Xr + (size_t)m * 256 + seg * 4);
        }
        #pragma unroll
        for (int r = 0; r < 2; r++) {
            int idx = t + r * 256;
            int k = idx >> 4, o4 = (idx & 15) << 2;
            cpa16(ws_u + (unsigned)((k * 72 + o4) * 4), g_Wt + (size_t)k * 320 + oc + o4);
        }
        cpa_commit();
    }

    for (int kc = 0; kc < 8; kc++) {
        const int buf = kc & 1;
        cpa_wait<0>();
        __syncthreads();
        if (kc < 7) {
            const int nb = buf ^ 1, kn = (kc + 1) * 32;
            #pragma unroll
            for (int r = 0; r < 4; r++) {
                int idx = t + r * 256;
                int m = idx >> 3, seg = idx & 7;
                cpa16(as_u + (unsigned)((nb * 4608 + m * 36 + seg * 4) * 4),
                      Xr + (size_t)m * 256 + kn + seg * 4);
            }
            #pragma unroll
            for (int r = 0; r < 2; r++) {
                int idx = t + r * 256;
                int k = idx >> 4, o4 = (idx & 15) << 2;
                cpa16(ws_u + (unsigned)((nb * 2304 + k * 72 + o4) * 4),
                      g_Wt + (size_t)(kn + k) * 320 + oc + o4);
            }
            cpa_commit();
        }
        const float* Ab = As + buf * 4608;
        const float* Wb = Ws + buf * 2304;
        #pragma unroll
        for (int hs = 0; hs < 4; hs++) {
            const int kb = hs * 8;
            uint32_t af[2][4];
            #pragma unroll
            for (int mt = 0; mt < 2; mt++) {
                const float* ar = Ab + (mbase + mt * 16 + g) * 36 + kb + tig;
                af[mt][0] = __float_as_uint(ar[0]);
                af[mt][1] = __float_as_uint(ar[8 * 36]);
                af[mt][2] = __float_as_uint(ar[4]);
                af[mt][3] = __float_as_uint(ar[8 * 36 + 4]);
            }
            #pragma unroll
            for (int nt = 0; nt < 4; nt++) {
                const float* br = Wb + (kb + tig) * 72 + nbase + nt * 8 + g;
                uint32_t bf[2];
                bf[0] = __float_as_uint(br[0]);
                bf[1] = __float_as_uint(br[4 * 72]);
                mma_tf32(acc[0][nt], af[0], bf);
                mma_tf32(acc[1][nt], af[1], bf);
            }
        }
    }
    __syncthreads();

    #pragma unroll
    for (int mt = 0; mt < 2; mt++)
        #pragma unroll
        for (int nt = 0; nt < 4; nt++) {
            int row = mbase + mt * 16 + g;
            int col = nbase + nt * 8 + 2 * tig;
            float b0 = g_bias[oc + col], b1 = g_bias[oc + col + 1];
            Ot[row][col]     = acc[mt][nt][0] + b0;
            Ot[row][col + 1] = acc[mt][nt][1] + b1;
            Ot[row + 8][col]     = acc[mt][nt][2] + b0;
            Ot[row + 8][col + 1] = acc[mt][nt][3] + b1;
        }
    __syncthreads();

    {
        const int c0v = ot * 64;
        int ww = t >> 1, half = t & 1;
        const float* src = &Ot[ww][half * 32];
        if (b > 0) {
            float* dst = g_vH + (((size_t)(b * 128 + ww)) * 128 + h) * 256 + c0v + half * 32;
            #pragma unroll
            for (int i = 0; i < 8; i++) ((float4*)dst)[i] = ((const float4*)src)[i];
            float* dw = g_vW + ((size_t)(b * 128 + h)) * 32768 + c0v;
            #pragma unroll
            for (int r = 0; r < 8; r++) {
                int e = (t + r * 256) << 2;
                int wI = e >> 6, cI = e & 63;
                *(float4*)(dw + (size_t)wI * 256 + cI) = *(const float4*)&Ot[wI][cI];
            }
        } else {
            float* dst = g_p0 + ((size_t)(h * 128 + ww)) * 320 + 64 + c0v + half * 32;
            #pragma unroll
            for (int i = 0; i < 8; i++) ((float4*)dst)[i] = ((const float4*)src)[i];
        }
    }
}

// ---- deformable bilinear sampling: grid (16384, 2), block 320 ----
__global__ void kern_sample()
{
    const int pt = blockIdx.x, br = blockIdx.y;
    const int k = pt >> 7, pos = pt & 127;
    float px, py;
    if (br == 0) {
        int r = pos + 1;
        px = (-1.0f + k * 0.015625f) + g_dX[r][0];
        py = (-1.0f + r * 0.015625f) + g_dX[r][1];
    } else {
        int ci = pos + 1;
        px = (-1.0f + ci * 0.015625f) + g_dY[ci][0];
        py = (-1.0f + k * 0.015625f) + g_dY[ci][1];
    }
    float fx = (px + 1.0f) * 0.5f * 127.0f;
    float fy = (py + 1.0f) * 0.5f * 127.0f;
    float x0f = floorf(fx), y0f = floorf(fy);
    float wx = fx - x0f, wy = fy - y0f;
    int x0 = (int)x0f, y0 = (int)y0f;
    bool vx0 = (x0 >= 0) && (x0 < 128);
    bool vx1 = (x0 + 1 >= 0) && (x0 + 1 < 128);
    bool vy0 = (y0 >= 0) && (y0 < 128);
    bool vy1 = (y0 + 1 >= 0) && (y0 + 1 < 128);

    const int c = threadIdx.x;
    float acc = 0.f;
    if (vx0 && vy0) acc += g_p0[((size_t)(y0 * 128 + x0)) * 320 + c] * ((1.f - wx) * (1.f - wy));
    if (vx1 && vy0) acc += g_p0[((size_t)(y0 * 128 + x0 + 1)) * 320 + c] * (wx * (1.f - wy));
    if (vx0 && vy1) acc += g_p0[((size_t)((y0 + 1) * 128 + x0)) * 320 + c] * ((1.f - wx) * wy);
    if (vx1 && vy1) acc += g_p0[((size_t)((y0 + 1) * 128 + x0 + 1)) * 320 + c] * (wx * wy);

    size_t lp = (size_t)k * 128 + pos;
    if (br == 0) {
        if (c < 32)      g_qH[lp * 32 + c] = acc;
        else if (c < 64) g_kH[lp * 32 + (c - 32)] = acc;
        else             g_vH[lp * 256 + (c - 64)] = acc;
    } else {
        if (c < 32)      g_qW[lp * 32 + c] = acc;
        else if (c < 64) g_kW[lp * 32 + (c - 32)] = acc;
        else             g_vW[lp * 256 + (c - 64)] = acc;
    }
}

// ---- per-line energy GEMM E = Q @ K^T: grid (512, 2), block 256 ----
__global__ __launch_bounds__(256) void kern_energy()
{
    __shared__ __align__(16) float Qt[32][132];
    __shared__ __align__(16) float Kt[32][132];
    const int l = blockIdx.x, br = blockIdx.y;
    const float* Q = (br ? g_qW : g_qH) + (size_t)l * 4096;
    const float* K = (br ? g_kW : g_kH) + (size_t)l * 4096;
    float* E = (br ? g_EW : g_EH) + (size_t)l * 16384;
    const int t = threadIdx.x;

    #pragma unroll
    for (int r = 0; r < 4; r++) {
        int lin = t + r * 256;
        int p = lin >> 3, c4 = (lin & 7) << 2;
        float4 q = *(const float4*)(Q + (size_t)p * 32 + c4);
        Qt[c4][p] = q.x; Qt[c4 + 1][p] = q.y; Qt[c4 + 2][p] = q.z; Qt[c4 + 3][p] = q.w;
        float4 kk = *(const float4*)(K + (size_t)p * 32 + c4);
        Kt[c4][p] = kk.x; Kt[c4 + 1][p] = kk.y; Kt[c4 + 2][p] = kk.z; Kt[c4 + 3][p] = kk.w;
    }
    __syncthreads();

    const int tj = t & 15, ti = t >> 4;
    const int i0 = ti * 8, j0 = tj * 8;
    ull acc2[8][4];
    #pragma unroll
    for (int u = 0; u < 8; u++)
        #pragma unroll
        for (int v = 0; v < 4; v++) acc2[u][v] = 0ULL;

    #pragma unroll
    for (int c = 0; c < 32; c++) {
        float4 qa = *(const float4*)&Qt[c][i0];
        float4 qb = *(const float4*)&Qt[c][i0 + 4];
        ull ad[8] = {dup2(qa.x), dup2(qa.y), dup2(qa.z), dup2(qa.w),
                     dup2(qb.x), dup2(qb.y), dup2(qb.z), dup2(qb.w)};
        const ull* kp = (const ull*)&Kt[c][j0];
        ull b0 = kp[0], b1 = kp[1], b2 = kp[2], b3 = kp[3];
        #pragma unroll
        for (int u = 0; u < 8; u++) {
            ffma2(acc2[u][0], ad[u], b0);
            ffma2(acc2[u][1], ad[u], b1);
            ffma2(acc2[u][2], ad[u], b2);
            ffma2(acc2[u][3], ad[u], b3);
        }
    }
    #pragma unroll
    for (int u = 0; u < 8; u++) {
        float2 p0 = u2f(acc2[u][0]), p1 = u2f(acc2[u][1]);
        float2 p2 = u2f(acc2[u][2]), p3 = u2f(acc2[u][3]);
        *(float4*)(E + (size_t)(i0 + u) * 128 + j0)     = make_float4(p0.x, p0.y, p1.x, p1.y);
        *(float4*)(E + (size_t)(i0 + u) * 128 + j0 + 4) = make_float4(p2.x, p2.y, p3.x, p3.y);
    }
}

// ---- joint softmax ----
__global__ void kern_softmax()
{
    int gw = (blockIdx.x * blockDim.x + threadIdx.x) >> 5;
    int lane = threadIdx.x & 31;
    if (gw >= 65536) return;
    int b = gw >> 14;
    int rem = gw & 16383;
    int h = rem >> 7, w = rem & 127;
    float* r1 = g_EH + (((size_t)(b * 128 + w)) * 128 + h) * 128;
    float* r2 = g_EW + (((size_t)(b * 128 + h)) * 128 + w) * 128;
    float4 a = *(float4*)(r1 + lane * 4);
    float4 c = *(float4*)(r2 + lane * 4);
    float e1[4] = {a.x, a.y, a.z, a.w};
    float e2[4] = {c.x, c.y, c.z, c.w};
    float m = -INFINITY;
    #pragma unroll
    for (int u = 0; u < 4; u++) {
        if (lane * 4 + u != h) m = fmaxf(m, e1[u]);
        m = fmaxf(m, e2[u]);
    }
    #pragma unroll
    for (int s = 16; s > 0; s >>= 1) m = fmaxf(m, __shfl_xor_sync(0xffffffffu, m, s));
    float sum = 0.f;
    #pragma unroll
    for (int u = 0; u < 4; u++) {
        e1[u] = (lane * 4 + u == h) ? 0.f : __expf(e1[u] - m);
        sum += e1[u];
        e2[u] = __expf(e2[u] - m);
        sum += e2[u];
    }
    #pragma unroll
    for (int s = 16; s > 0; s >>= 1) sum += __shfl_xor_sync(0xffffffffu, sum, s);
    float inv = 1.0f / sum;
    *(float4*)(r1 + lane * 4) = make_float4(e1[0] * inv, e1[1] * inv, e1[2] * inv, e1[3] * inv);
    *(float4*)(r2 + lane * 4) = make_float4(e2[0] * inv, e2[1] * inv, e2[2] * inv, e2[3] * inv);
}

// ---- per-line output GEMM via mma.sync tf32 ----
// smem: As[2][128][36] (36864 B) + Vs[2][32][136] (34816 B) = 71680 B
#define OSM_TOTAL 71680

__global__ __launch_bounds__(256) void kern_out_mma()
{
    extern __shared__ __align__(16) float osm[];
    float* As = osm;             // [2][128][36]
    float* Vs = osm + 9216;      // [2][32][136]
    const int l = blockIdx.x, chf = blockIdx.y, br = blockIdx.z;
    const float* A = (br ? g_EW : g_EH) + (size_t)l * 16384;
    const float* V = (br ? g_vW : g_vH) + (size_t)l * 32768 + chf * 128;
    float* O = (br ? g_rO : g_cO) + (size_t)l * 32768 + chf * 128;
    const int t = threadIdx.x;
    const int w = t >> 5, lane = t & 31;
    const int g = lane >> 2, tig = lane & 3;
    const int kbase = (w >> 1) * 32, cbase = (w & 1) * 64;
    const unsigned as_u = (unsigned)__cvta_generic_to_shared(As);
    const unsigned vs_u = (unsigned)__cvta_generic_to_shared(Vs);

    float acc[2][8][4];
    #pragma unroll
    for (int mt = 0; mt < 2; mt++)
        #pragma unroll
        for (int nt = 0; nt < 8; nt++)
            #pragma unroll
            for (int i = 0; i < 4; i++) acc[mt][nt][i] = 0.f;

    {
        #pragma unroll
        for (int r = 0; r < 4; r++) {
            int idx = t + r * 256;
            int k = idx >> 3, seg = idx & 7;
            cpa16(as_u + (unsigned)((k * 36 + seg * 4) * 4), A + (size_t)k * 128 + seg * 4);
        }
        #pragma unroll
        for (int r = 0; r < 4; r++) {
            int idx = t + r * 256;
            int hh = idx >> 5, seg = idx & 31;
            cpa16(vs_u + (unsigned)((hh * 136 + seg * 4) * 4), V + (size_t)hh * 256 + seg * 4);
        }
        cpa_commit();
    }

    for (int hc = 0; hc < 4; hc++) {
        const int buf = hc & 1;
        cpa_wait<0>();
        __syncthreads();
        if (hc < 3) {
            const int nb = buf ^ 1, hn = (hc + 1) * 32;
            #pragma unroll
            for (int r = 0; r < 4; r++) {
                int idx = t + r * 256;
                int k = idx >> 3, seg = idx & 7;
                cpa16(as_u + (unsigned)((nb * 4608 + k * 36 + seg * 4) * 4),
                      A + (size_t)k * 128 + hn + seg * 4);
            }
            #pragma unroll
            for (int r = 0; r < 4; r++) {
                int idx = t + r * 256;
                int hh = idx >> 5, seg = idx & 31;
                cpa16(vs_u + (unsigned)((nb * 4352 + hh * 136 + seg * 4) * 4),
                      V + (size_t)(hn + hh) * 256 + seg * 4);
            }
            cpa_commit();
        }
        const float* Ab = As + buf * 4608;
        const float* Vb = Vs + buf * 4352;
        #pragma unroll
        for (int hs = 0; hs < 4; hs++) {
            const int hb = hs * 8;
            uint32_t af[2][4];
            #pragma unroll
            for (int mt = 0; mt < 2; mt++) {
                const float* ar = Ab + (kbase + mt * 16 + g) * 36 + hb + tig;
                af[mt][0] = __float_as_uint(ar[0]);
                af[mt][1] = __float_as_uint(ar[8 * 36]);
                af[mt][2] = __float_as_uint(ar[4]);
                af[mt][3] = __float_as_uint(ar[8 * 36 + 4]);
            }
            #pragma unroll
            for (int nt = 0; nt < 8; nt++) {
                const float* vr = Vb + (hb + tig) * 136 + cbase + nt * 8 + g;
                uint32_t bf[2];
                bf[0] = __float_as_uint(vr[0]);
                bf[1] = __float_as_uint(vr[4 * 136]);
                mma_tf32(acc[0][nt], af[0], bf);
                mma_tf32(acc[1][nt], af[1], bf);
            }
        }
    }

    #pragma unroll
    for (int mt = 0; mt < 2; mt++)
        #pragma unroll
        for (int nt = 0; nt < 8; nt++) {
            int row = kbase + mt * 16 + g;
            int col = cbase + nt * 8 + 2 * tig;
            *(float2*)(O + (size_t)row * 256 + col)       = make_float2(acc[mt][nt][0], acc[mt][nt][1]);
            *(float2*)(O + (size_t)(row + 8) * 256 + col) = make_float2(acc[mt][nt][2], acc[mt][nt][3]);
        }
}

// ---- combine ----
__global__ void kern_combine(const float* __restrict__ x, const float* __restrict__ gamma,
                             float* __restrict__ out)
{
    __shared__ __align__(16) float s[32][132];
    const int h = blockIdx.x, ct = blockIdx.y, b = blockIdx.z;
    const int c0 = ct * 32, t = threadIdx.x;
    #pragma unroll
    for (int r = 0; r < 4; r++) {
        int lin = t + r * 256;
        int w = lin >> 3, c4 = (lin & 7) << 2;
        float4 a = *(const float4*)(g_cO + (((size_t)(b * 128 + w)) * 128 + h) * 256 + c0 + c4);
        float4 bb = *(const float4*)(g_rO + (((size_t)(b * 128 + h)) * 128 + w) * 256 + c0 + c4);
        s[c4][w] = a.x + bb.x; s[c4 + 1][w] = a.y + bb.y;
        s[c4 + 2][w] = a.z + bb.z; s[c4 + 3][w] = a.w + bb.w;
    }
    __syncthreads();
    float g = gamma[0];
    #pragma unroll
    for (int r = 0; r < 4; r++) {
        int lin = t + r * 256;
        int c = lin >> 5, w4 = (lin & 31) << 2;
        size_t oidx = (((size_t)b * 256 + c0 + c) * 128 + h) * 128 + w4;
        float4 xv = *(const float4*)(x + oidx);
        float4 o;
        o.x = g * s[c][w4] + xv.x;
        o.y = g * s[c][w4 + 1] + xv.y;
        o.z = g * s[c][w4 + 2] + xv.z;
        o.w = g * s[c][w4 + 3] + xv.w;
        *(float4*)(out + oidx) = o;
    }
}

extern "C" void kernel_launch(void* const* d_in, const int* in_sizes, int n_in,
                              void* d_out, int out_size)
{
    const float* x      = (const float*)d_in[0];
    const float* Wq     = (const float*)d_in[1];
    const float* bq     = (const float*)d_in[2];
    const float* Wk     = (const float*)d_in[3];
    const float* bk     = (const float*)d_in[4];
    const float* Wv     = (const float*)d_in[5];
    const float* bv     = (const float*)d_in[6];
    const float* gamma  = (const float*)d_in[7];
    const float* offs   = (const float*)d_in[8];
    float* out = (float*)d_out;

    cudaFuncSetAttribute(kern_out_mma, cudaFuncAttributeMaxDynamicSharedMemorySize, OSM_TOTAL);
    cudaFuncSetAttribute(kern_projv, cudaFuncAttributeMaxDynamicSharedMemorySize, PSM_TOTAL);
    cudaFuncSetAttribute(kern_projqk_mma, cudaFuncAttributeMaxDynamicSharedMemorySize, PSM_TOTAL);

    kern_prep<<<1, 512>>>(offs, out, out_size - 1);
    kern_wt<<<320, 256>>>(Wq, bq, Wk, bk, Wv, bv);
    kern_xT<<<dim3(4, 128, 4), 256>>>(x);
    kern_projqk_mma<<<dim3(128, 1, 4), 256, PSM_TOTAL>>>();
    kern_projv<<<dim3(128, 4, 4), 256, PSM_TOTAL>>>();
    kern_sample<<<dim3(16384, 2), 320>>>();
    kern_energy<<<dim3(512, 2), 256>>>();
    kern_softmax<<<8192, 256>>>();
    kern_out_mma<<<dim3(512, 2, 2), 256, OSM_TOTAL>>>();
    kern_combine<<<dim3(128, 8, 4), 256>>>(x, gamma, out);
}